// round 3
// baseline (speedup 1.0000x reference)
#include <cuda_runtime.h>

#define HID   128
#define EF    4
#define NG    20
#define ZK    280      // 2*HID + NG + EF
#define NZK   256      // 2*HID
#define TILE  64
#define ZS    68       // padded SMEM row stride (floats): 272B, 16B-aligned
#define MAXN  50000

// -------- device scratch (no cudaMalloc allowed) --------
__device__ float g_mi[(size_t)MAXN * HID];
__device__ float g_dx[(size_t)MAXN * 3];
__device__ int   g_idx64;

// -------- packed f32x2 helpers (Blackwell) --------
__device__ __forceinline__ unsigned long long pack2(float x, float y) {
    unsigned long long r;
    asm("mov.b64 %0, {%1,%2};" : "=l"(r) : "f"(x), "f"(y));
    return r;
}
__device__ __forceinline__ void unpack2(unsigned long long v, float& x, float& y) {
    asm("mov.b64 {%0,%1}, %2;" : "=f"(x), "=f"(y) : "l"(v));
}
__device__ __forceinline__ unsigned long long fma2(unsigned long long a,
                                                   unsigned long long b,
                                                   unsigned long long c) {
    unsigned long long d;
    asm("fma.rn.f32x2 %0, %1, %2, %3;" : "=l"(d) : "l"(a), "l"(b), "l"(c));
    return d;
}
__device__ __forceinline__ float siluf(float v) {
    // v * sigmoid(v) == v / (1 + e^-v); __expf rel-err ~2^-21, well under 1e-3
    return __fdividef(v, 1.0f + __expf(-v));
}

// -------- init: zero accumulators + detect edge_index dtype --------
__global__ void init_kernel(const int* __restrict__ ei32, int nMi, int nDx) {
    if (blockIdx.x == 0 && threadIdx.x == 0) {
        // If stored as int64 (values < 2^31, nonneg), every odd int32 word is 0.
        int flag = 1;
        #pragma unroll 4
        for (int i = 0; i < 64; i++)
            if (ei32[2 * i + 1] != 0) { flag = 0; break; }
        g_idx64 = flag;
    }
    int total = nMi + nDx;
    for (int i = blockIdx.x * blockDim.x + threadIdx.x; i < total;
         i += gridDim.x * blockDim.x) {
        if (i < nMi) g_mi[i] = 0.0f;
        else         g_dx[i - nMi] = 0.0f;
    }
}

// -------- fused edge kernel --------
// 128 threads; TILE=64 edges per block. Thread t owns output column t of every
// edge GEMM; edge pairs live packed in f32x2 accumulators.
// SMEM (k-major, stride ZS):
//   ZT [ZK][ZS]   z features   (overlaid by MT [HID][ZS] = mij after GEMM1 reads end)
//   BT [HID][ZS]  t1           (overlaid by GT = silu(g1) after GEMM2 reads end)
__global__ void __launch_bounds__(128)
edge_kernel(const float* __restrict__ h, const float* __restrict__ x,
            const void* __restrict__ eidx, const float* __restrict__ eattr,
            const float* __restrict__ We1, const float* __restrict__ be1,
            const float* __restrict__ We2, const float* __restrict__ be2,
            const float* __restrict__ Winf, const float* __restrict__ binf,
            const float* __restrict__ Wx1, const float* __restrict__ bx1,
            const float* __restrict__ Wx2, int E)
{
    extern __shared__ float sm[];
    float* ZT   = sm;                          // ZK*ZS
    float* BT   = sm + ZK * ZS;                // HID*ZS
    int*   sSrc = (int*)(sm + ZK * ZS + HID * ZS);
    int*   sDst = sSrc + TILE;
    float* sD   = (float*)(sDst + TILE);
    float* sRX  = sD + TILE;                   // TILE*3
    float* sEij = sRX + TILE * 3;
    float* sXG  = sEij + TILE;

    const int tid = threadIdx.x;
    const long long ebase = (long long)blockIdx.x * TILE;
    const int nE = (int)min((long long)TILE, (long long)E - ebase);

    // ---- phase A: indices, geometry, gaussian feats, edge_attr ----
    if (tid < TILE) {
        const int e = tid;
        const long long eg = ebase + min(e, nE - 1);
        int s_, d_;
        if (g_idx64) {
            const long long* p = (const long long*)eidx;
            s_ = (int)p[eg];
            d_ = (int)p[(long long)E + eg];
        } else {
            const int* p = (const int*)eidx;
            s_ = p[eg];
            d_ = p[(long long)E + eg];
        }
        sSrc[e] = s_; sDst[e] = d_;
        float rx = x[d_ * 3 + 0] - x[s_ * 3 + 0];
        float ry = x[d_ * 3 + 1] - x[s_ * 3 + 1];
        float rz = x[d_ * 3 + 2] - x[s_ * 3 + 2];
        float dd = sqrtf(rx * rx + ry * ry + rz * rz + 1e-8f);
        sD[e] = dd;
        sRX[e * 3 + 0] = rx; sRX[e * 3 + 1] = ry; sRX[e * 3 + 2] = rz;
        const float step  = 10.0f / 19.0f;
        const float coeff = -0.5f / (step * step);
        #pragma unroll
        for (int g = 0; g < NG; g++) {
            float t = dd - step * (float)g;
            ZT[(2 * HID + g) * ZS + e] = __expf(coeff * t * t);
        }
        #pragma unroll
        for (int a = 0; a < EF; a++)
            ZT[(2 * HID + NG + a) * ZS + e] = eattr[eg * EF + a];
    }
    __syncthreads();

    // ---- gather h[dst], h[src] into ZT (coalesced 512B rows, mostly L2 hits) ----
    #pragma unroll 8
    for (int e = 0; e < TILE; e++) {
        const int d_ = sDst[e], s_ = sSrc[e];
        ZT[tid * ZS + e]         = h[(size_t)d_ * HID + tid];
        ZT[(HID + tid) * ZS + e] = h[(size_t)s_ * HID + tid];
    }
    __syncthreads();

    unsigned long long acc[TILE / 2];

    // ---- GEMM1: t1 = silu(z @ We1 + be1) ----
    #pragma unroll
    for (int i = 0; i < TILE / 2; i++) acc[i] = 0ULL;
    #pragma unroll 2
    for (int k = 0; k < ZK; k++) {
        const float w = __ldg(&We1[k * HID + tid]);
        const unsigned long long w2 = pack2(w, w);
        const ulonglong2* z2 = (const ulonglong2*)(ZT + k * ZS);
        #pragma unroll
        for (int i = 0; i < TILE / 4; i++) {
            ulonglong2 v = z2[i];
            acc[2 * i]     = fma2(v.x, w2, acc[2 * i]);
            acc[2 * i + 1] = fma2(v.y, w2, acc[2 * i + 1]);
        }
    }
    {
        const float b = be1[tid];
        #pragma unroll
        for (int i = 0; i < TILE / 2; i++) {
            float a0, a1; unpack2(acc[i], a0, a1);
            float2 t; t.x = siluf(a0 + b); t.y = siluf(a1 + b);
            *(float2*)(BT + tid * ZS + 2 * i) = t;
        }
    }
    __syncthreads();

    // ---- GEMM2: mij = silu(t1 @ We2 + be2) -> MT (overlays ZT) ----
    #pragma unroll
    for (int i = 0; i < TILE / 2; i++) acc[i] = 0ULL;
    #pragma unroll 2
    for (int k = 0; k < HID; k++) {
        const float w = __ldg(&We2[k * HID + tid]);
        const unsigned long long w2 = pack2(w, w);
        const ulonglong2* z2 = (const ulonglong2*)(BT + k * ZS);
        #pragma unroll
        for (int i = 0; i < TILE / 4; i++) {
            ulonglong2 v = z2[i];
            acc[2 * i]     = fma2(v.x, w2, acc[2 * i]);
            acc[2 * i + 1] = fma2(v.y, w2, acc[2 * i + 1]);
        }
    }
    float* MT = ZT;   // ZT fully consumed -> safe overlay (all GEMM1 reads precede
                      // the t1-write sync; GEMM2 touches only BT)
    {
        const float b = be2[tid];
        #pragma unroll
        for (int i = 0; i < TILE / 2; i++) {
            float a0, a1; unpack2(acc[i], a0, a1);
            float2 t; t.x = siluf(a0 + b); t.y = siluf(a1 + b);
            *(float2*)(MT + tid * ZS + 2 * i) = t;
        }
    }
    __syncthreads();  // S1: MT visible to all

    // ---- eij = sigmoid(mij . Winf + binf), one thread per edge (conflict-free) ----
    if (tid < TILE) {
        float s = binf[0];
        #pragma unroll 4
        for (int k = 0; k < HID; k++)
            s += MT[k * ZS + tid] * Winf[k];
        sEij[tid] = __fdividef(1.0f, 1.0f + __expf(-s));
    }

    // ---- GEMM3: g = silu(mij @ Wx1 + bx1) -> GT (overlays BT) ----
    #pragma unroll
    for (int i = 0; i < TILE / 2; i++) acc[i] = 0ULL;
    #pragma unroll 2
    for (int k = 0; k < HID; k++) {
        const float w = __ldg(&Wx1[k * HID + tid]);
        const unsigned long long w2 = pack2(w, w);
        const ulonglong2* z2 = (const ulonglong2*)(MT + k * ZS);
        #pragma unroll
        for (int i = 0; i < TILE / 4; i++) {
            ulonglong2 v = z2[i];
            acc[2 * i]     = fma2(v.x, w2, acc[2 * i]);
            acc[2 * i + 1] = fma2(v.y, w2, acc[2 * i + 1]);
        }
    }
    float* GT = BT;
    {
        const float b = bx1[tid];
        #pragma unroll
        for (int i = 0; i < TILE / 2; i++) {
            float a0, a1; unpack2(acc[i], a0, a1);
            float2 t; t.x = siluf(a0 + b); t.y = siluf(a1 + b);
            *(float2*)(GT + tid * ZS + 2 * i) = t;
        }
    }
    __syncthreads();  // S2: GT + sEij visible to all

    // ---- xg = tanh(g . Wx2) ----
    if (tid < TILE) {
        float s = 0.0f;
        #pragma unroll 4
        for (int k = 0; k < HID; k++)
            s += GT[k * ZS + tid] * Wx2[k];
        sXG[tid] = tanhf(s);
    }

    // ---- scatter: mi[dst] += mij*eij  (coalesced per-warp REDG) ----
    #pragma unroll 2
    for (int e = 0; e < nE; e++) {
        float v = MT[tid * ZS + e] * sEij[e];
        atomicAdd(&g_mi[(size_t)sDst[e] * HID + tid], v);
    }
    // ---- scatter: dx[dst] += rel_x/(d+1)*xg  (sXG/sRX/sD self-written by this thread) ----
    if (tid < nE) {
        const int e = tid, d_ = sDst[e];
        const float f = __fdividef(sXG[e], sD[e] + 1.0f);
        atomicAdd(&g_dx[d_ * 3 + 0], sRX[e * 3 + 0] * f);
        atomicAdd(&g_dx[d_ * 3 + 1], sRX[e * 3 + 1] * f);
        atomicAdd(&g_dx[d_ * 3 + 2], sRX[e * 3 + 2] * f);
    }
}

// -------- node kernel: h_out = h + MLP([mi, h]); x_out = x + dx*mask --------
__global__ void __launch_bounds__(128)
node_kernel(const float* __restrict__ h, const float* __restrict__ x,
            const float* __restrict__ mask,
            const float* __restrict__ Wn1, const float* __restrict__ bn1,
            const float* __restrict__ Wn2, const float* __restrict__ bn2,
            float* __restrict__ out, int N)
{
    extern __shared__ float sm[];
    float* NZT = sm;              // NZK*ZS
    float* UT  = sm + NZK * ZS;   // HID*ZS

    const int tid = threadIdx.x;
    const int n0  = blockIdx.x * TILE;
    const int nN  = min(TILE, N - n0);

    #pragma unroll 8
    for (int e = 0; e < TILE; e++) {
        const int nd = n0 + min(e, nN - 1);
        NZT[tid * ZS + e]         = g_mi[(size_t)nd * HID + tid];
        NZT[(HID + tid) * ZS + e] = h[(size_t)nd * HID + tid];
    }
    __syncthreads();

    unsigned long long acc[TILE / 2];
    #pragma unroll
    for (int i = 0; i < TILE / 2; i++) acc[i] = 0ULL;
    #pragma unroll 2
    for (int k = 0; k < NZK; k++) {
        const float w = __ldg(&Wn1[k * HID + tid]);
        const unsigned long long w2 = pack2(w, w);
        const ulonglong2* z2 = (const ulonglong2*)(NZT + k * ZS);
        #pragma unroll
        for (int i = 0; i < TILE / 4; i++) {
            ulonglong2 v = z2[i];
            acc[2 * i]     = fma2(v.x, w2, acc[2 * i]);
            acc[2 * i + 1] = fma2(v.y, w2, acc[2 * i + 1]);
        }
    }
    {
        const float b = bn1[tid];
        #pragma unroll
        for (int i = 0; i < TILE / 2; i++) {
            float a0, a1; unpack2(acc[i], a0, a1);
            float2 t; t.x = siluf(a0 + b); t.y = siluf(a1 + b);
            *(float2*)(UT + tid * ZS + 2 * i) = t;
        }
    }
    __syncthreads();

    #pragma unroll
    for (int i = 0; i < TILE / 2; i++) acc[i] = 0ULL;
    #pragma unroll 2
    for (int k = 0; k < HID; k++) {
        const float w = __ldg(&Wn2[k * HID + tid]);
        const unsigned long long w2 = pack2(w, w);
        const ulonglong2* z2 = (const ulonglong2*)(UT + k * ZS);
        #pragma unroll
        for (int i = 0; i < TILE / 4; i++) {
            ulonglong2 v = z2[i];
            acc[2 * i]     = fma2(v.x, w2, acc[2 * i]);
            acc[2 * i + 1] = fma2(v.y, w2, acc[2 * i + 1]);
        }
    }
    {
        const float b = bn2[tid];
        #pragma unroll
        for (int i = 0; i < TILE / 2; i++) {
            float a0, a1; unpack2(acc[i], a0, a1);
            const int e0 = 2 * i, e1 = 2 * i + 1;
            if (e0 < nN)
                out[(size_t)(n0 + e0) * HID + tid] = h[(size_t)(n0 + e0) * HID + tid] + a0 + b;
            if (e1 < nN)
                out[(size_t)(n0 + e1) * HID + tid] = h[(size_t)(n0 + e1) * HID + tid] + a1 + b;
        }
    }
    if (tid < nN) {
        const int nd = n0 + tid;
        const float m = mask[nd];
        const size_t xo = (size_t)N * HID;
        out[xo + nd * 3 + 0] = x[nd * 3 + 0] + g_dx[nd * 3 + 0] * m;
        out[xo + nd * 3 + 1] = x[nd * 3 + 1] + g_dx[nd * 3 + 1] * m;
        out[xo + nd * 3 + 2] = x[nd * 3 + 2] + g_dx[nd * 3 + 2] * m;
    }
}

extern "C" void kernel_launch(void* const* d_in, const int* in_sizes, int n_in,
                              void* d_out, int out_size) {
    const float* h    = (const float*)d_in[0];
    const float* x    = (const float*)d_in[1];
    const void*  ei   = d_in[2];
    const float* mask = (const float*)d_in[3];
    const float* ea   = (const float*)d_in[4];
    const float* We1  = (const float*)d_in[5];
    const float* be1  = (const float*)d_in[6];
    const float* We2  = (const float*)d_in[7];
    const float* be2  = (const float*)d_in[8];
    const float* Winf = (const float*)d_in[9];
    const float* binf = (const float*)d_in[10];
    const float* Wx1  = (const float*)d_in[11];
    const float* bx1  = (const float*)d_in[12];
    const float* Wx2  = (const float*)d_in[13];
    const float* Wn1  = (const float*)d_in[14];
    const float* bn1  = (const float*)d_in[15];
    const float* Wn2  = (const float*)d_in[16];
    const float* bn2  = (const float*)d_in[17];
    float* out = (float*)d_out;

    const int N = in_sizes[0] / HID;
    const int E = in_sizes[2] / 2;

    const int edge_smem = (ZK * ZS + HID * ZS) * 4        // ZT + BT
                        + TILE * 2 * 4                    // sSrc, sDst
                        + TILE * 6 * 4;                   // sD, sRX(3), sEij, sXG
    const int node_smem = (NZK * ZS + HID * ZS) * 4;

    cudaFuncSetAttribute(edge_kernel, cudaFuncAttributeMaxDynamicSharedMemorySize, edge_smem);
    cudaFuncSetAttribute(node_kernel, cudaFuncAttributeMaxDynamicSharedMemorySize, node_smem);

    init_kernel<<<2048, 256>>>((const int*)ei, N * HID, N * 3);
    edge_kernel<<<(E + TILE - 1) / TILE, 128, edge_smem>>>(
        h, x, ei, ea, We1, be1, We2, be2, Winf, binf, Wx1, bx1, Wx2, E);
    node_kernel<<<(N + TILE - 1) / TILE, 128, node_smem>>>(
        h, x, mask, Wn1, bn1, Wn2, bn2, out, N);
}

// round 5
// speedup vs baseline: 1.4306x; 1.4306x over previous
#include <cuda_runtime.h>

#define HID   128
#define EF    4
#define NG    20
#define ZK    280      // 2*HID + NG + EF
#define NZK   256      // 2*HID
#define TILE  64
#define ZS    68       // padded SMEM row stride (floats): 272B, 16B-aligned
#define MAXN  50000

// -------- device scratch (no cudaMalloc allowed) --------
__device__ float g_mi[(size_t)MAXN * HID];
__device__ float g_dx[(size_t)MAXN * 3];
__device__ int   g_idx64;

// -------- packed f32x2 helpers (Blackwell FFMA2) --------
__device__ __forceinline__ unsigned long long pack2(float x, float y) {
    unsigned long long r;
    asm("mov.b64 %0, {%1,%2};" : "=l"(r) : "f"(x), "f"(y));
    return r;
}
__device__ __forceinline__ void unpack2(unsigned long long v, float& x, float& y) {
    asm("mov.b64 {%0,%1}, %2;" : "=f"(x), "=f"(y) : "l"(v));
}
__device__ __forceinline__ unsigned long long fma2(unsigned long long a,
                                                   unsigned long long b,
                                                   unsigned long long c) {
    unsigned long long d;
    asm("fma.rn.f32x2 %0, %1, %2, %3;" : "=l"(d) : "l"(a), "l"(b), "l"(c));
    return d;
}
__device__ __forceinline__ float siluf(float v) {
    return __fdividef(v, 1.0f + __expf(-v));
}

// 16 f32x2 accumulators = 32 edges per thread (this thread's half-tile).
// All GEMMs: thread owns output column `col`, edges [e0, e0+32).
#define GEMM_BODY(Zb, kk, ww) do {                                            \
    unsigned long long w2_ = pack2((ww), (ww));                               \
    const ulonglong2* z2_ = (const ulonglong2*)((Zb) + (kk) * ZS) + half * 8; \
    _Pragma("unroll")                                                         \
    for (int i_ = 0; i_ < 8; i_++) {                                          \
        ulonglong2 v_ = z2_[i_];                                              \
        acc[2*i_]   = fma2(v_.x, w2_, acc[2*i_]);                             \
        acc[2*i_+1] = fma2(v_.y, w2_, acc[2*i_+1]);                           \
    }                                                                         \
} while (0)

#define RUN_GEMM(W, Zb, K) do {                                               \
    _Pragma("unroll")                                                         \
    for (int i_ = 0; i_ < 16; i_++) acc[i_] = 0ULL;                           \
    float w_ = __ldg(&(W)[col]);                                              \
    _Pragma("unroll 4")                                                       \
    for (int k_ = 0; k_ < (K) - 1; k_++) {                                    \
        float wn_ = __ldg(&(W)[(k_ + 1) * HID + col]);                        \
        GEMM_BODY(Zb, k_, w_);                                                \
        w_ = wn_;                                                             \
    }                                                                         \
    GEMM_BODY(Zb, (K) - 1, w_);                                               \
} while (0)

#define WB_SILU(dst, bptr) do {                                               \
    const float b_ = (bptr)[col];                                             \
    _Pragma("unroll")                                                         \
    for (int i_ = 0; i_ < 16; i_++) {                                         \
        float a0_, a1_; unpack2(acc[i_], a0_, a1_);                           \
        float2 t_; t_.x = siluf(a0_ + b_); t_.y = siluf(a1_ + b_);            \
        *(float2*)((dst) + col * ZS + e0 + 2 * i_) = t_;                      \
    }                                                                         \
} while (0)

// -------- init: zero accumulators + detect edge_index dtype --------
__global__ void init_kernel(const int* __restrict__ ei32, int nMi, int nDx) {
    if (blockIdx.x == 0 && threadIdx.x == 0) {
        int flag = 1;
        #pragma unroll 4
        for (int i = 0; i < 64; i++)
            if (ei32[2 * i + 1] != 0) { flag = 0; break; }
        g_idx64 = flag;
    }
    int total = nMi + nDx;
    for (int i = blockIdx.x * blockDim.x + threadIdx.x; i < total;
         i += gridDim.x * blockDim.x) {
        if (i < nMi) g_mi[i] = 0.0f;
        else         g_dx[i - nMi] = 0.0f;
    }
}

// -------- fused edge kernel (256 threads, 64 edges/block) --------
// SMEM:
//   ZT [ZK][ZS]   z features  (overlaid by MT [HID][ZS] = mij after GEMM1)
//   BT [HID][ZS]  t1          (overlaid by GT = silu(g1) after GEMM2)
__global__ void __launch_bounds__(256, 2)
edge_kernel(const float* __restrict__ h, const float* __restrict__ x,
            const void* __restrict__ eidx, const float* __restrict__ eattr,
            const float* __restrict__ We1, const float* __restrict__ be1,
            const float* __restrict__ We2, const float* __restrict__ be2,
            const float* __restrict__ Winf, const float* __restrict__ binf,
            const float* __restrict__ Wx1, const float* __restrict__ bx1,
            const float* __restrict__ Wx2, int E)
{
    extern __shared__ float sm[];
    float* ZT   = sm;                          // ZK*ZS
    float* BT   = sm + ZK * ZS;                // HID*ZS
    int*   sSrc = (int*)(sm + ZK * ZS + HID * ZS);
    int*   sDst = sSrc + TILE;
    float* sD   = (float*)(sDst + TILE);
    float* sRX  = sD + TILE;                   // TILE*3
    float* sEij = sRX + TILE * 3;
    float* sXG  = sEij + TILE;

    const int tid  = threadIdx.x;
    const int col  = tid & (HID - 1);          // output column 0..127
    const int half = tid >> 7;                 // 0: edges 0..31, 1: edges 32..63
    const int e0   = half * 32;
    const long long ebase = (long long)blockIdx.x * TILE;
    const int nE = (int)min((long long)TILE, (long long)E - ebase);

    // ---- phase A: indices, geometry, gaussian feats, edge_attr ----
    if (tid < TILE) {
        const int e = tid;
        const long long eg = ebase + min(e, nE - 1);
        int s_, d_;
        if (g_idx64) {
            const long long* p = (const long long*)eidx;
            s_ = (int)p[eg];
            d_ = (int)p[(long long)E + eg];
        } else {
            const int* p = (const int*)eidx;
            s_ = p[eg];
            d_ = p[(long long)E + eg];
        }
        sSrc[e] = s_; sDst[e] = d_;
        float rx = x[d_ * 3 + 0] - x[s_ * 3 + 0];
        float ry = x[d_ * 3 + 1] - x[s_ * 3 + 1];
        float rz = x[d_ * 3 + 2] - x[s_ * 3 + 2];
        float dd = sqrtf(rx * rx + ry * ry + rz * rz + 1e-8f);
        sD[e] = dd;
        sRX[e * 3 + 0] = rx; sRX[e * 3 + 1] = ry; sRX[e * 3 + 2] = rz;
        const float step  = 10.0f / 19.0f;
        const float coeff = -0.5f / (step * step);
        #pragma unroll
        for (int g = 0; g < NG; g++) {
            float t = dd - step * (float)g;
            ZT[(2 * HID + g) * ZS + e] = __expf(coeff * t * t);
        }
        #pragma unroll
        for (int a = 0; a < EF; a++)
            ZT[(2 * HID + NG + a) * ZS + e] = eattr[eg * EF + a];
    }
    __syncthreads();

    // ---- gather h[dst], h[src] into ZT (each thread: its half's 32 edges) ----
    #pragma unroll 4
    for (int i = 0; i < 32; i++) {
        const int e = e0 + i;
        const int d_ = sDst[e], s_ = sSrc[e];
        ZT[col * ZS + e]         = h[(size_t)d_ * HID + col];
        ZT[(HID + col) * ZS + e] = h[(size_t)s_ * HID + col];
    }
    __syncthreads();

    unsigned long long acc[16];

    // ---- GEMM1: t1 = silu(z @ We1 + be1) -> BT ----
    RUN_GEMM(We1, ZT, ZK);
    WB_SILU(BT, be1);
    __syncthreads();

    // ---- GEMM2: mij = silu(t1 @ We2 + be2) -> MT (overlays ZT) ----
    RUN_GEMM(We2, BT, HID);
    float* MT = ZT;   // all ZT reads done before previous sync
    WB_SILU(MT, be2);
    __syncthreads();  // S1: MT visible

    // ---- eij = sigmoid(mij . Winf + binf), one thread per edge ----
    if (tid < TILE) {
        float s = binf[0];
        #pragma unroll 4
        for (int k = 0; k < HID; k++)
            s += MT[k * ZS + tid] * Winf[k];
        sEij[tid] = __fdividef(1.0f, 1.0f + __expf(-s));
    }

    // ---- GEMM3: g = silu(mij @ Wx1 + bx1) -> GT (overlays BT) ----
    RUN_GEMM(Wx1, MT, HID);
    float* GT = BT;
    WB_SILU(GT, bx1);
    __syncthreads();  // S2: GT + sEij visible

    // ---- xg = tanh(g . Wx2) ----
    if (tid < TILE) {
        float s = 0.0f;
        #pragma unroll 4
        for (int k = 0; k < HID; k++)
            s += GT[k * ZS + tid] * Wx2[k];
        sXG[tid] = tanhf(s);
    }

    // ---- scatter: mi[dst] += mij*eij (coalesced 128B REDG per warp) ----
    #pragma unroll 2
    for (int i = 0; i < 32; i++) {
        const int e = e0 + i;
        if (e < nE) {
            float v = MT[col * ZS + e] * sEij[e];
            atomicAdd(&g_mi[(size_t)sDst[e] * HID + col], v);
        }
    }
    // ---- scatter: dx[dst] += rel_x/(d+1)*xg (sXG self-written by this thread) ----
    if (tid < nE) {
        const int e = tid, d_ = sDst[e];
        const float f = __fdividef(sXG[e], sD[e] + 1.0f);
        atomicAdd(&g_dx[d_ * 3 + 0], sRX[e * 3 + 0] * f);
        atomicAdd(&g_dx[d_ * 3 + 1], sRX[e * 3 + 1] * f);
        atomicAdd(&g_dx[d_ * 3 + 2], sRX[e * 3 + 2] * f);
    }
}

// -------- node kernel: h_out = h + MLP([mi, h]); x_out = x + dx*mask --------
__global__ void __launch_bounds__(256, 2)
node_kernel(const float* __restrict__ h, const float* __restrict__ x,
            const float* __restrict__ mask,
            const float* __restrict__ Wn1, const float* __restrict__ bn1,
            const float* __restrict__ Wn2, const float* __restrict__ bn2,
            float* __restrict__ out, int N)
{
    extern __shared__ float sm[];
    float* NZT = sm;              // NZK*ZS
    float* UT  = sm + NZK * ZS;   // HID*ZS

    const int tid  = threadIdx.x;
    const int col  = tid & (HID - 1);
    const int half = tid >> 7;
    const int e0   = half * 32;
    const int n0   = blockIdx.x * TILE;
    const int nN   = min(TILE, N - n0);

    #pragma unroll 4
    for (int i = 0; i < 32; i++) {
        const int e = e0 + i;
        const int nd = n0 + min(e, nN - 1);
        NZT[col * ZS + e]         = g_mi[(size_t)nd * HID + col];
        NZT[(HID + col) * ZS + e] = h[(size_t)nd * HID + col];
    }
    __syncthreads();

    unsigned long long acc[16];

    RUN_GEMM(Wn1, NZT, NZK);
    WB_SILU(UT, bn1);
    __syncthreads();

    RUN_GEMM(Wn2, UT, HID);
    {
        const float b = bn2[col];
        #pragma unroll
        for (int i = 0; i < 16; i++) {
            float a0, a1; unpack2(acc[i], a0, a1);
            const int u0 = e0 + 2 * i, u1 = e0 + 2 * i + 1;
            if (u0 < nN)
                out[(size_t)(n0 + u0) * HID + col] = h[(size_t)(n0 + u0) * HID + col] + a0 + b;
            if (u1 < nN)
                out[(size_t)(n0 + u1) * HID + col] = h[(size_t)(n0 + u1) * HID + col] + a1 + b;
        }
    }
    if (tid < nN) {
        const int nd = n0 + tid;
        const float m = mask[nd];
        const size_t xo = (size_t)N * HID;
        out[xo + nd * 3 + 0] = x[nd * 3 + 0] + g_dx[nd * 3 + 0] * m;
        out[xo + nd * 3 + 1] = x[nd * 3 + 1] + g_dx[nd * 3 + 1] * m;
        out[xo + nd * 3 + 2] = x[nd * 3 + 2] + g_dx[nd * 3 + 2] * m;
    }
}

extern "C" void kernel_launch(void* const* d_in, const int* in_sizes, int n_in,
                              void* d_out, int out_size) {
    const float* h    = (const float*)d_in[0];
    const float* x    = (const float*)d_in[1];
    const void*  ei   = d_in[2];
    const float* mask = (const float*)d_in[3];
    const float* ea   = (const float*)d_in[4];
    const float* We1  = (const float*)d_in[5];
    const float* be1  = (const float*)d_in[6];
    const float* We2  = (const float*)d_in[7];
    const float* be2  = (const float*)d_in[8];
    const float* Winf = (const float*)d_in[9];
    const float* binf = (const float*)d_in[10];
    const float* Wx1  = (const float*)d_in[11];
    const float* bx1  = (const float*)d_in[12];
    const float* Wx2  = (const float*)d_in[13];
    const float* Wn1  = (const float*)d_in[14];
    const float* bn1  = (const float*)d_in[15];
    const float* Wn2  = (const float*)d_in[16];
    const float* bn2  = (const float*)d_in[17];
    float* out = (float*)d_out;

    const int N = in_sizes[0] / HID;
    const int E = in_sizes[2] / 2;

    const int edge_smem = (ZK * ZS + HID * ZS) * 4 + TILE * 2 * 4 + TILE * 6 * 4;
    const int node_smem = (NZK * ZS + HID * ZS) * 4;

    cudaFuncSetAttribute(edge_kernel, cudaFuncAttributeMaxDynamicSharedMemorySize, edge_smem);
    cudaFuncSetAttribute(node_kernel, cudaFuncAttributeMaxDynamicSharedMemorySize, node_smem);

    init_kernel<<<2048, 256>>>((const int*)ei, N * HID, N * 3);
    edge_kernel<<<(E + TILE - 1) / TILE, 256, edge_smem>>>(
        h, x, ei, ea, We1, be1, We2, be2, Winf, binf, Wx1, bx1, Wx2, E);
    node_kernel<<<(N + TILE - 1) / TILE, 256, node_smem>>>(
        h, x, mask, Wn1, bn1, Wn2, bn2, out, N);
}

// round 7
// speedup vs baseline: 3.2639x; 2.2814x over previous
#include <cuda_runtime.h>

#define HID   128
#define EF    4
#define NG    20
#define ZK    280      // 2*HID + NG + EF
#define NZK   256      // 2*HID
#define TILE  64
#define SA    292      // z SMEM row stride (floats): conflict-free A-frags, 16B-aligned
#define SB    132      // activation SMEM row stride
#define MAXN  50000

// -------- device scratch (no cudaMalloc allowed) --------
__device__ float g_mi[(size_t)MAXN * HID];
__device__ float g_dx[(size_t)MAXN * 3];
__device__ int   g_idx64;
// tf32-rounded weight copies (filled by init_kernel)
__device__ float g_w1c[ZK * HID];
__device__ float g_w2c[HID * HID];
__device__ float g_w3c[HID * HID];
__device__ float g_wn1c[NZK * HID];
__device__ float g_wn2c[HID * HID];

// -------- helpers --------
__device__ __forceinline__ float to_tf32(float x) {
    float r; asm("cvt.rna.tf32.f32 %0, %1;" : "=f"(r) : "f"(x)); return r;
}
__device__ __forceinline__ float siluf(float v) {
    return __fdividef(v, 1.0f + __expf(-v));
}
__device__ __forceinline__ void mma8(float* d, const unsigned* a, const unsigned* b) {
    asm volatile(
        "mma.sync.aligned.m16n8k8.row.col.f32.tf32.tf32.f32 "
        "{%0,%1,%2,%3},{%4,%5,%6,%7},{%8,%9},{%0,%1,%2,%3};"
        : "+f"(d[0]), "+f"(d[1]), "+f"(d[2]), "+f"(d[3])
        : "r"(a[0]), "r"(a[1]), "r"(a[2]), "r"(a[3]), "r"(b[0]), "r"(b[1]));
}
__device__ __forceinline__ void red4(float* p, float a, float b, float c, float d) {
    asm volatile("red.global.add.v4.f32 [%0], {%1,%2,%3,%4};"
                 :: "l"(p), "f"(a), "f"(b), "f"(c), "f"(d) : "memory");
}

// -------- warp GEMM: D[64 x 128] += A[64 x K] @ W[K x 128] --------
// 8 warps: warp = mh + 2*nq; warp tile 32(M) x 32(N); m16n8k8 atoms 2x4.
// A in SMEM (row-major, stride sa); W read directly from gmem (tf32 values),
// distance-1 register prefetch on B fragments.
template <int NK8>
__device__ __forceinline__ void warp_gemm(const float* __restrict__ As, int sa,
                                          const float* __restrict__ W,
                                          int mh, int nq, int g, int tig,
                                          float acc[2][4][4])
{
    #pragma unroll
    for (int mm = 0; mm < 2; mm++)
        #pragma unroll
        for (int na = 0; na < 4; na++)
            #pragma unroll
            for (int i = 0; i < 4; i++) acc[mm][na][i] = 0.0f;

    const float* a0 = As + (mh * 32 + g) * sa + tig;
    const float* bp = W + tig * HID + nq * 32 + g;

    unsigned bc[4][2], bn[4][2];
    #pragma unroll
    for (int na = 0; na < 4; na++) {
        bc[na][0] = __float_as_uint(__ldg(bp + na * 8));
        bc[na][1] = __float_as_uint(__ldg(bp + 4 * HID + na * 8));
    }

    #pragma unroll 4
    for (int k8 = 0; k8 < NK8; k8++) {
        if (k8 + 1 < NK8) {
            const float* bpk = bp + (k8 + 1) * 8 * HID;
            #pragma unroll
            for (int na = 0; na < 4; na++) {
                bn[na][0] = __float_as_uint(__ldg(bpk + na * 8));
                bn[na][1] = __float_as_uint(__ldg(bpk + 4 * HID + na * 8));
            }
        }
        unsigned a[2][4];
        const float* ak = a0 + k8 * 8;
        #pragma unroll
        for (int mm = 0; mm < 2; mm++) {
            const float* am = ak + mm * 16 * sa;
            a[mm][0] = __float_as_uint(am[0]);
            a[mm][1] = __float_as_uint(am[8 * sa]);
            a[mm][2] = __float_as_uint(am[4]);
            a[mm][3] = __float_as_uint(am[8 * sa + 4]);
        }
        #pragma unroll
        for (int mm = 0; mm < 2; mm++)
            #pragma unroll
            for (int na = 0; na < 4; na++)
                mma8(acc[mm][na], a[mm], bc[na]);
        #pragma unroll
        for (int na = 0; na < 4; na++) { bc[na][0] = bn[na][0]; bc[na][1] = bn[na][1]; }
    }
}

// epilogue: dst[r][c] = to_tf32(silu(acc + bias[c]))  (SMEM, stride sd)
__device__ __forceinline__ void epi_silu(float* dst, int sd, const float* __restrict__ bias,
                                         int mh, int nq, int g, int tig, float acc[2][4][4])
{
    #pragma unroll
    for (int mm = 0; mm < 2; mm++) {
        const int r0 = mh * 32 + mm * 16 + g;
        #pragma unroll
        for (int na = 0; na < 4; na++) {
            const int c = nq * 32 + na * 8 + tig * 2;
            const float b0 = __ldg(bias + c), b1 = __ldg(bias + c + 1);
            float2 v;
            v.x = to_tf32(siluf(acc[mm][na][0] + b0));
            v.y = to_tf32(siluf(acc[mm][na][1] + b1));
            *(float2*)(dst + r0 * sd + c) = v;
            v.x = to_tf32(siluf(acc[mm][na][2] + b0));
            v.y = to_tf32(siluf(acc[mm][na][3] + b1));
            *(float2*)(dst + (r0 + 8) * sd + c) = v;
        }
    }
}

// -------- init: zero accumulators, detect idx dtype, tf32-round weights --------
__global__ void init_kernel(const int* __restrict__ ei32,
                            const float* __restrict__ We1, const float* __restrict__ We2,
                            const float* __restrict__ Wx1, const float* __restrict__ Wn1,
                            const float* __restrict__ Wn2, int N)
{
    if (blockIdx.x == 0 && threadIdx.x == 0) {
        int flag = 1;
        for (int i = 0; i < 64; i++)
            if (ei32[2 * i + 1] != 0) { flag = 0; break; }
        g_idx64 = flag;
    }
    const int nMi = N * HID, nDx = N * 3;
    const int nW1 = ZK * HID, nW = HID * HID, nWn1 = NZK * HID;
    const int total = nMi + nDx + nW1 + 3 * nW + nWn1;
    for (int i = blockIdx.x * blockDim.x + threadIdx.x; i < total;
         i += gridDim.x * blockDim.x) {
        int j = i;
        if (j < nMi) { g_mi[j] = 0.0f; continue; }            j -= nMi;
        if (j < nDx) { g_dx[j] = 0.0f; continue; }            j -= nDx;
        if (j < nW1) { g_w1c[j] = to_tf32(We1[j]); continue; } j -= nW1;
        if (j < nW)  { g_w2c[j] = to_tf32(We2[j]); continue; } j -= nW;
        if (j < nW)  { g_w3c[j] = to_tf32(Wx1[j]); continue; } j -= nW;
        if (j < nWn1){ g_wn1c[j] = to_tf32(Wn1[j]); continue; } j -= nWn1;
        g_wn2c[j] = to_tf32(Wn2[j]);
    }
}

// -------- fused edge kernel: 64 edges/block, 256 threads, tensor-core GEMMs --------
__global__ void __launch_bounds__(256, 2)
edge_kernel(const float* __restrict__ h, const float* __restrict__ x,
            const void* __restrict__ eidx, const float* __restrict__ eattr,
            const float* __restrict__ be1, const float* __restrict__ be2,
            const float* __restrict__ Winf, const float* __restrict__ binf,
            const float* __restrict__ bx1, const float* __restrict__ Wx2, int E)
{
    extern __shared__ float sm[];
    float* zA   = sm;                       // [64][SA]  z (row-major); later mij (stride SB)
    float* B1   = sm + TILE * SA;           // [64][SB]  t1, then g
    int*   sSrc = (int*)(B1 + TILE * SB);
    int*   sDst = sSrc + TILE;
    float* sD   = (float*)(sDst + TILE);
    float* sRX  = sD + TILE;                // [64][3]
    float* sEij = sRX + TILE * 3;
    float* sXG  = sEij + TILE;

    const int tid  = threadIdx.x;
    const int lane = tid & 31, wid = tid >> 5;
    const int mh = wid & 1, nq = wid >> 1;
    const int g = lane >> 2, tig = lane & 3;
    const long long ebase = (long long)blockIdx.x * TILE;
    const int nE = (int)min((long long)TILE, (long long)E - ebase);

    // ---- phase A: indices, geometry, gaussian feats, edge_attr ----
    if (tid < TILE) {
        const int e = tid;
        const long long eg = ebase + min(e, nE - 1);
        int s_, d_;
        if (g_idx64) {
            const long long* p = (const long long*)eidx;
            s_ = (int)p[eg]; d_ = (int)p[(long long)E + eg];
        } else {
            const int* p = (const int*)eidx;
            s_ = p[eg]; d_ = p[(long long)E + eg];
        }
        sSrc[e] = s_; sDst[e] = d_;
        float rx = x[d_ * 3 + 0] - x[s_ * 3 + 0];
        float ry = x[d_ * 3 + 1] - x[s_ * 3 + 1];
        float rz = x[d_ * 3 + 2] - x[s_ * 3 + 2];
        float dd = sqrtf(rx * rx + ry * ry + rz * rz + 1e-8f);
        sD[e] = dd;
        sRX[e * 3 + 0] = rx; sRX[e * 3 + 1] = ry; sRX[e * 3 + 2] = rz;
        const float step  = 10.0f / 19.0f;
        const float coeff = -0.5f / (step * step);
        #pragma unroll
        for (int gg = 0; gg < NG; gg++) {
            float t = dd - step * (float)gg;
            zA[e * SA + 2 * HID + gg] = to_tf32(__expf(coeff * t * t));
        }
        #pragma unroll
        for (int a_ = 0; a_ < EF; a_++)
            zA[e * SA + 2 * HID + NG + a_] = to_tf32(eattr[eg * EF + a_]);
    }
    __syncthreads();

    // ---- gather h[dst], h[src] -> zA rows (float4 coalesced, cvt to tf32) ----
    #pragma unroll
    for (int it = 0; it < 8; it++) {
        const int e = wid + it * 8;
        const float4 vd = __ldg((const float4*)(h + (size_t)sDst[e] * HID) + lane);
        const float4 vs = __ldg((const float4*)(h + (size_t)sSrc[e] * HID) + lane);
        float4 w;
        w.x = to_tf32(vd.x); w.y = to_tf32(vd.y); w.z = to_tf32(vd.z); w.w = to_tf32(vd.w);
        *(float4*)(zA + e * SA + lane * 4) = w;
        w.x = to_tf32(vs.x); w.y = to_tf32(vs.y); w.z = to_tf32(vs.z); w.w = to_tf32(vs.w);
        *(float4*)(zA + e * SA + HID + lane * 4) = w;
    }
    __syncthreads();

    float acc[2][4][4];

    // ---- GEMM1: t1 = silu(z @ We1 + be1) -> B1 ----
    warp_gemm<ZK / 8>(zA, SA, g_w1c, mh, nq, g, tig, acc);
    epi_silu(B1, SB, be1, mh, nq, g, tig, acc);
    __syncthreads();

    // ---- GEMM2: mij = silu(t1 @ We2 + be2) -> MT (overlays zA, stride SB) ----
    warp_gemm<HID / 8>(B1, SB, g_w2c, mh, nq, g, tig, acc);
    float* MT = zA;
    epi_silu(MT, SB, be2, mh, nq, g, tig, acc);
    __syncthreads();   // S1: MT visible

    // ---- eij = sigmoid(mij . Winf + binf) (fp32) ----
    if (tid < TILE) {
        float s = binf[0];
        #pragma unroll 4
        for (int k = 0; k < HID; k++)
            s += MT[tid * SB + k] * __ldg(&Winf[k]);
        sEij[tid] = __fdividef(1.0f, 1.0f + __expf(-s));
    }

    // ---- GEMM3: gx = silu(mij @ Wx1 + bx1) -> GT (overlays B1) ----
    warp_gemm<HID / 8>(MT, SB, g_w3c, mh, nq, g, tig, acc);
    float* GT = B1;
    epi_silu(GT, SB, bx1, mh, nq, g, tig, acc);
    __syncthreads();   // S2: GT + sEij visible

    // ---- xg = tanh(gx . Wx2) ----
    if (tid < TILE) {
        float s = 0.0f;
        #pragma unroll 4
        for (int k = 0; k < HID; k++)
            s += GT[tid * SB + k] * __ldg(&Wx2[k]);
        sXG[tid] = tanhf(s);
    }

    // ---- scatter: mi[dst] += mij*eij via red.global.add.v4.f32 ----
    #pragma unroll 2
    for (int i = 0; i < 8; i++) {
        const int e = wid * 8 + i;
        if (e < nE) {
            const float4 v = *(const float4*)(MT + e * SB + lane * 4);
            const float sc = sEij[e];
            red4(&g_mi[(size_t)sDst[e] * HID + lane * 4],
                 v.x * sc, v.y * sc, v.z * sc, v.w * sc);
        }
    }
    // ---- scatter: dx[dst] += rel_x/(d+1)*xg ----
    if (tid < nE) {
        const int e = tid, d_ = sDst[e];
        const float f = __fdividef(sXG[e], sD[e] + 1.0f);
        atomicAdd(&g_dx[d_ * 3 + 0], sRX[e * 3 + 0] * f);
        atomicAdd(&g_dx[d_ * 3 + 1], sRX[e * 3 + 1] * f);
        atomicAdd(&g_dx[d_ * 3 + 2], sRX[e * 3 + 2] * f);
    }
}

// -------- node kernel: h_out = h + MLP([mi, h]); x_out = x + dx*mask --------
__global__ void __launch_bounds__(256, 2)
node_kernel(const float* __restrict__ h, const float* __restrict__ x,
            const float* __restrict__ mask,
            const float* __restrict__ bn1, const float* __restrict__ bn2,
            float* __restrict__ out, int N)
{
    extern __shared__ float sm[];
    float* zA = sm;                 // [64][SA] : [mi | h]
    float* B1 = sm + TILE * SA;     // [64][SB] : u

    const int tid  = threadIdx.x;
    const int lane = tid & 31, wid = tid >> 5;
    const int mh = wid & 1, nq = wid >> 1;
    const int g = lane >> 2, tig = lane & 3;
    const int n0 = blockIdx.x * TILE;
    const int nN = min(TILE, N - n0);

    #pragma unroll
    for (int it = 0; it < 8; it++) {
        const int e  = wid + it * 8;
        const int nd = n0 + min(e, nN - 1);
        const float4 vm = __ldg((const float4*)(g_mi + (size_t)nd * HID) + lane);
        const float4 vh = __ldg((const float4*)(h + (size_t)nd * HID) + lane);
        float4 w;
        w.x = to_tf32(vm.x); w.y = to_tf32(vm.y); w.z = to_tf32(vm.z); w.w = to_tf32(vm.w);
        *(float4*)(zA + e * SA + lane * 4) = w;
        w.x = to_tf32(vh.x); w.y = to_tf32(vh.y); w.z = to_tf32(vh.z); w.w = to_tf32(vh.w);
        *(float4*)(zA + e * SA + HID + lane * 4) = w;
    }
    __syncthreads();

    float acc[2][4][4];

    warp_gemm<NZK / 8>(zA, SA, g_wn1c, mh, nq, g, tig, acc);
    epi_silu(B1, SB, bn1, mh, nq, g, tig, acc);
    __syncthreads();

    warp_gemm<HID / 8>(B1, SB, g_wn2c, mh, nq, g, tig, acc);
    {
        #pragma unroll
        for (int mm = 0; mm < 2; mm++) {
            const int r0 = mh * 32 + mm * 16 + g;
            #pragma unroll
            for (int na = 0; na < 4; na++) {
                const int c = nq * 32 + na * 8 + tig * 2;
                const float b0 = __ldg(bn2 + c), b1 = __ldg(bn2 + c + 1);
                if (r0 < nN) {
                    const size_t o = (size_t)(n0 + r0) * HID + c;
                    out[o]     = h[o]     + acc[mm][na][0] + b0;
                    out[o + 1] = h[o + 1] + acc[mm][na][1] + b1;
                }
                if (r0 + 8 < nN) {
                    const size_t o = (size_t)(n0 + r0 + 8) * HID + c;
                    out[o]     = h[o]     + acc[mm][na][2] + b0;
                    out[o + 1] = h[o + 1] + acc[mm][na][3] + b1;
                }
            }
        }
    }
    if (tid < nN) {
        const int nd = n0 + tid;
        const float m = mask[nd];
        const size_t xo = (size_t)N * HID;
        out[xo + nd * 3 + 0] = x[nd * 3 + 0] + g_dx[nd * 3 + 0] * m;
        out[xo + nd * 3 + 1] = x[nd * 3 + 1] + g_dx[nd * 3 + 1] * m;
        out[xo + nd * 3 + 2] = x[nd * 3 + 2] + g_dx[nd * 3 + 2] * m;
    }
}

extern "C" void kernel_launch(void* const* d_in, const int* in_sizes, int n_in,
                              void* d_out, int out_size) {
    const float* h    = (const float*)d_in[0];
    const float* x    = (const float*)d_in[1];
    const void*  ei   = d_in[2];
    const float* mask = (const float*)d_in[3];
    const float* ea   = (const float*)d_in[4];
    const float* We1  = (const float*)d_in[5];
    const float* be1  = (const float*)d_in[6];
    const float* We2  = (const float*)d_in[7];
    const float* be2  = (const float*)d_in[8];
    const float* Winf = (const float*)d_in[9];
    const float* binf = (const float*)d_in[10];
    const float* Wx1  = (const float*)d_in[11];
    const float* bx1  = (const float*)d_in[12];
    const float* Wx2  = (const float*)d_in[13];
    const float* Wn1  = (const float*)d_in[14];
    const float* bn1  = (const float*)d_in[15];
    const float* Wn2  = (const float*)d_in[16];
    const float* bn2  = (const float*)d_in[17];
    float* out = (float*)d_out;

    const int N = in_sizes[0] / HID;
    const int E = in_sizes[2] / 2;

    const int smem = (TILE * SA + TILE * SB + TILE * 8) * 4;

    cudaFuncSetAttribute(edge_kernel, cudaFuncAttributeMaxDynamicSharedMemorySize, smem);
    cudaFuncSetAttribute(node_kernel, cudaFuncAttributeMaxDynamicSharedMemorySize, smem);

    init_kernel<<<2048, 256>>>((const int*)ei, We1, We2, Wx1, Wn1, Wn2, N);
    edge_kernel<<<(E + TILE - 1) / TILE, 256, smem>>>(
        h, x, ei, ea, be1, be2, Winf, binf, bx1, Wx2, E);
    node_kernel<<<(N + TILE - 1) / TILE, 256, smem>>>(
        h, x, mask, bn1, bn2, out, N);
}

// round 10
// speedup vs baseline: 3.7327x; 1.1436x over previous
#include <cuda_runtime.h>

#define HID   128
#define EF    4
#define NG    20
#define ZK    280      // 2*HID + NG + EF  (35 k8-steps)
#define NZK   256      // 2*HID            (32 k8-steps)
#define TE    128      // edge tile (edge kernel)
#define TN    64       // node tile (node kernel)
#define SA    292      // z SMEM row stride (floats): conflict-free, 16B-aligned
#define SB    132      // activation SMEM row stride
#define MAXN  50000

// -------- device scratch (no cudaMalloc allowed) --------
__device__ float g_mi[(size_t)MAXN * HID];
__device__ float g_dx[(size_t)MAXN * 3];
__device__ int   g_idx64;
// fragment-packed tf32 weights (filled by init_kernel)
__device__ float g_w1c[ZK * HID];
__device__ float g_w2c[HID * HID];
__device__ float g_w3c[HID * HID];
__device__ float g_wn1c[NZK * HID];
__device__ float g_wn2c[HID * HID];

// -------- helpers --------
__device__ __forceinline__ float to_tf32(float x) {
    float r; asm("cvt.rna.tf32.f32 %0, %1;" : "=f"(r) : "f"(x)); return r;
}
__device__ __forceinline__ float siluf(float v) {
    return __fdividef(v, 1.0f + __expf(-v));
}
__device__ __forceinline__ void mma8(float* d, const unsigned* a, const unsigned* b) {
    asm volatile(
        "mma.sync.aligned.m16n8k8.row.col.f32.tf32.tf32.f32 "
        "{%0,%1,%2,%3},{%4,%5,%6,%7},{%8,%9},{%0,%1,%2,%3};"
        : "+f"(d[0]), "+f"(d[1]), "+f"(d[2]), "+f"(d[3])
        : "r"(a[0]), "r"(a[1]), "r"(a[2]), "r"(a[3]), "r"(b[0]), "r"(b[1]));
}
__device__ __forceinline__ void red4(float* p, float a, float b, float c, float d) {
    asm volatile("red.global.add.v4.f32 [%0], {%1,%2,%3,%4};"
                 :: "l"(p), "f"(a), "f"(b), "f"(c), "f"(d) : "memory");
}

// -------- fragment packing --------
// Packed layout: dst[(((k8*4 + cg)*32 + lane)*8) + na*2 + j]
//   = tf32( src[(k8*8 + tig + j*4)*HID + cg*32 + na*8 + g] ),  tig=lane&3, g=lane>>2
// => per k8-step a lane's 8 B-values are 32B contiguous (2 x LDG.128 per warp step).
__device__ __forceinline__ void pack_w(float* dst, const float* __restrict__ src, int i) {
    const int j = i & 1, na = (i >> 1) & 3, lane = (i >> 3) & 31;
    const int cg = (i >> 8) & 3, k8 = i >> 10;
    const int tig = lane & 3, gg = lane >> 2;
    dst[i] = to_tf32(src[(k8 * 8 + tig + j * 4) * HID + cg * 32 + na * 8 + gg]);
}

// -------- warp GEMM with packed weights --------
// Warp tile 32(M) x 32(N). A in SMEM row-major stride sa (rows mrow0..mrow0+31).
// Wp packed as above; warp reads its nq column-group; distance-2 prefetch.
template <int NK8>
__device__ __forceinline__ void warp_gemm(const float* __restrict__ As, int sa,
                                          const float* __restrict__ Wp,
                                          int mrow0, int nq, int g, int tig, int lane,
                                          float acc[2][4][4])
{
    #pragma unroll
    for (int mm = 0; mm < 2; mm++)
        #pragma unroll
        for (int na = 0; na < 4; na++)
            #pragma unroll
            for (int i = 0; i < 4; i++) acc[mm][na][i] = 0.0f;

    const float4* wp = (const float4*)Wp + ((size_t)nq * 32 + lane) * 2;
    const float*  a0 = As + (mrow0 + g) * sa + tig;
    // per-k8 advance: 4 col-groups * 32 lanes * 8 floats = 256 float4
    float4 c0 = __ldg(wp + 0),   c1 = __ldg(wp + 1);
    float4 n0 = __ldg(wp + 256), n1 = __ldg(wp + 257);

    #pragma unroll 2
    for (int k8 = 0; k8 < NK8; k8++) {
        const float4 f0 = c0, f1 = c1;
        c0 = n0; c1 = n1;
        if (k8 + 2 < NK8) {
            n0 = __ldg(wp + (size_t)(k8 + 2) * 256);
            n1 = __ldg(wp + (size_t)(k8 + 2) * 256 + 1);
        }
        unsigned bc[4][2] = {
            { __float_as_uint(f0.x), __float_as_uint(f0.y) },
            { __float_as_uint(f0.z), __float_as_uint(f0.w) },
            { __float_as_uint(f1.x), __float_as_uint(f1.y) },
            { __float_as_uint(f1.z), __float_as_uint(f1.w) } };
        unsigned a[2][4];
        const float* ak = a0 + k8 * 8;
        #pragma unroll
        for (int mm = 0; mm < 2; mm++) {
            const float* am = ak + mm * 16 * sa;
            a[mm][0] = __float_as_uint(am[0]);
            a[mm][1] = __float_as_uint(am[8 * sa]);
            a[mm][2] = __float_as_uint(am[4]);
            a[mm][3] = __float_as_uint(am[8 * sa + 4]);
        }
        #pragma unroll
        for (int mm = 0; mm < 2; mm++)
            #pragma unroll
            for (int na = 0; na < 4; na++)
                mma8(acc[mm][na], a[mm], bc[na]);
    }
}

// epilogue: dst[r][c] = tf32(silu(acc + bias[c]))  (SMEM, stride sd)
__device__ __forceinline__ void epi_silu(float* dst, int sd, const float* __restrict__ bias,
                                         int mrow0, int nq, int g, int tig, float acc[2][4][4])
{
    #pragma unroll
    for (int mm = 0; mm < 2; mm++) {
        const int r0 = mrow0 + mm * 16 + g;
        #pragma unroll
        for (int na = 0; na < 4; na++) {
            const int c = nq * 32 + na * 8 + tig * 2;
            const float b0 = __ldg(bias + c), b1 = __ldg(bias + c + 1);
            float2 v;
            v.x = to_tf32(siluf(acc[mm][na][0] + b0));
            v.y = to_tf32(siluf(acc[mm][na][1] + b1));
            *(float2*)(dst + r0 * sd + c) = v;
            v.x = to_tf32(siluf(acc[mm][na][2] + b0));
            v.y = to_tf32(siluf(acc[mm][na][3] + b1));
            *(float2*)(dst + (r0 + 8) * sd + c) = v;
        }
    }
}

// -------- init: zero accumulators, detect idx dtype, pack tf32 weights --------
__global__ void init_kernel(const int* __restrict__ ei32,
                            const float* __restrict__ We1, const float* __restrict__ We2,
                            const float* __restrict__ Wx1, const float* __restrict__ Wn1,
                            const float* __restrict__ Wn2, int N)
{
    if (blockIdx.x == 0 && threadIdx.x == 0) {
        int flag = 1;
        for (int i = 0; i < 64; i++)
            if (ei32[2 * i + 1] != 0) { flag = 0; break; }
        g_idx64 = flag;
    }
    const int nMi = N * HID, nDx = N * 3;
    const int nW1 = ZK * HID, nW = HID * HID, nWn1 = NZK * HID;
    const int total = nMi + nDx + nW1 + 3 * nW + nWn1;
    for (int i = blockIdx.x * blockDim.x + threadIdx.x; i < total;
         i += gridDim.x * blockDim.x) {
        int j = i;
        if (j < nMi) { g_mi[j] = 0.0f; continue; }              j -= nMi;
        if (j < nDx) { g_dx[j] = 0.0f; continue; }              j -= nDx;
        if (j < nW1) { pack_w(g_w1c, We1, j); continue; }       j -= nW1;
        if (j < nW)  { pack_w(g_w2c, We2, j); continue; }       j -= nW;
        if (j < nW)  { pack_w(g_w3c, Wx1, j); continue; }       j -= nW;
        if (j < nWn1){ pack_w(g_wn1c, Wn1, j); continue; }      j -= nWn1;
        pack_w(g_wn2c, Wn2, j);
    }
}

// -------- fused edge kernel: 128 edges/block, 512 threads, tensor-core GEMMs --------
__global__ void __launch_bounds__(512, 1)
edge_kernel(const float* __restrict__ h, const float* __restrict__ x,
            const void* __restrict__ eidx, const float* __restrict__ eattr,
            const float* __restrict__ be1, const float* __restrict__ be2,
            const float* __restrict__ Winf, const float* __restrict__ binf,
            const float* __restrict__ bx1, const float* __restrict__ Wx2, int E)
{
    extern __shared__ float sm[];
    float* zA   = sm;                       // [TE][SA]  z; later mij (stride SB)
    float* B1   = sm + TE * SA;             // [TE][SB]  t1, then g
    int*   sSrc = (int*)(B1 + TE * SB);
    int*   sDst = sSrc + TE;
    float* sD   = (float*)(sDst + TE);
    float* sRX  = sD + TE;                  // [TE][3]
    float* sEij = sRX + TE * 3;
    float* sXG  = sEij + TE;

    const int tid  = threadIdx.x;
    const int lane = tid & 31, wid = tid >> 5;
    const int mrow0 = (wid & 3) * 32, nq = wid >> 2;   // 4(M) x 4(N) warp grid
    const int g = lane >> 2, tig = lane & 3;
    const long long ebase = (long long)blockIdx.x * TE;
    const int nE = (int)min((long long)TE, (long long)E - ebase);

    // ---- phase A: indices, geometry, gaussian feats, edge_attr ----
    if (tid < TE) {
        const int e = tid;
        const long long eg = ebase + min(e, nE - 1);
        int s_, d_;
        if (g_idx64) {
            const long long* p = (const long long*)eidx;
            s_ = (int)p[eg]; d_ = (int)p[(long long)E + eg];
        } else {
            const int* p = (const int*)eidx;
            s_ = p[eg]; d_ = p[(long long)E + eg];
        }
        sSrc[e] = s_; sDst[e] = d_;
        float rx = x[d_ * 3 + 0] - x[s_ * 3 + 0];
        float ry = x[d_ * 3 + 1] - x[s_ * 3 + 1];
        float rz = x[d_ * 3 + 2] - x[s_ * 3 + 2];
        float dd = sqrtf(rx * rx + ry * ry + rz * rz + 1e-8f);
        sD[e] = dd;
        sRX[e * 3 + 0] = rx; sRX[e * 3 + 1] = ry; sRX[e * 3 + 2] = rz;
        const float step  = 10.0f / 19.0f;
        const float coeff = -0.5f / (step * step);
        #pragma unroll
        for (int gg = 0; gg < NG; gg++) {
            float t = dd - step * (float)gg;
            zA[e * SA + 2 * HID + gg] = to_tf32(__expf(coeff * t * t));
        }
        #pragma unroll
        for (int a_ = 0; a_ < EF; a_++)
            zA[e * SA + 2 * HID + NG + a_] = to_tf32(eattr[eg * EF + a_]);
    }
    __syncthreads();

    // ---- gather h[dst], h[src] -> zA rows (float4 coalesced, cvt to tf32) ----
    #pragma unroll
    for (int it = 0; it < 8; it++) {
        const int e = wid + it * 16;
        const float4 vd = __ldg((const float4*)(h + (size_t)sDst[e] * HID) + lane);
        const float4 vs = __ldg((const float4*)(h + (size_t)sSrc[e] * HID) + lane);
        float4 w;
        w.x = to_tf32(vd.x); w.y = to_tf32(vd.y); w.z = to_tf32(vd.z); w.w = to_tf32(vd.w);
        *(float4*)(zA + e * SA + lane * 4) = w;
        w.x = to_tf32(vs.x); w.y = to_tf32(vs.y); w.z = to_tf32(vs.z); w.w = to_tf32(vs.w);
        *(float4*)(zA + e * SA + HID + lane * 4) = w;
    }
    __syncthreads();

    float acc[2][4][4];

    // ---- GEMM1: t1 = silu(z @ We1 + be1) -> B1 ----
    warp_gemm<ZK / 8>(zA, SA, g_w1c, mrow0, nq, g, tig, lane, acc);
    epi_silu(B1, SB, be1, mrow0, nq, g, tig, acc);
    __syncthreads();

    // ---- GEMM2: mij = silu(t1 @ We2 + be2) -> MT (overlays zA, stride SB) ----
    warp_gemm<HID / 8>(B1, SB, g_w2c, mrow0, nq, g, tig, lane, acc);
    float* MT = zA;
    epi_silu(MT, SB, be2, mrow0, nq, g, tig, acc);
    __syncthreads();   // S1: MT visible

    // ---- eij = sigmoid(mij . Winf + binf) ----
    if (tid < TE) {
        float s = binf[0];
        #pragma unroll 4
        for (int k = 0; k < HID; k++)
            s += MT[tid * SB + k] * __ldg(&Winf[k]);
        sEij[tid] = __fdividef(1.0f, 1.0f + __expf(-s));
    }

    // ---- GEMM3: gx = silu(mij @ Wx1 + bx1) -> GT (overlays B1) ----
    warp_gemm<HID / 8>(MT, SB, g_w3c, mrow0, nq, g, tig, lane, acc);
    float* GT = B1;
    epi_silu(GT, SB, bx1, mrow0, nq, g, tig, acc);
    __syncthreads();   // S2: GT + sEij visible

    // ---- xg = tanh(gx . Wx2) ----
    if (tid < TE) {
        float s = 0.0f;
        #pragma unroll 4
        for (int k = 0; k < HID; k++)
            s += GT[tid * SB + k] * __ldg(&Wx2[k]);
        sXG[tid] = tanhf(s);
    }

    // ---- scatter: mi[dst] += mij*eij via red.global.add.v4.f32 ----
    #pragma unroll 2
    for (int i = 0; i < 8; i++) {
        const int e = wid * 8 + i;
        if (e < nE) {
            const float4 v = *(const float4*)(MT + e * SB + lane * 4);
            const float sc = sEij[e];
            red4(&g_mi[(size_t)sDst[e] * HID + lane * 4],
                 v.x * sc, v.y * sc, v.z * sc, v.w * sc);
        }
    }
    // ---- scatter: dx[dst] += rel_x/(d+1)*xg ----
    if (tid < nE) {
        const int e = tid, d_ = sDst[e];
        const float f = __fdividef(sXG[e], sD[e] + 1.0f);
        atomicAdd(&g_dx[d_ * 3 + 0], sRX[e * 3 + 0] * f);
        atomicAdd(&g_dx[d_ * 3 + 1], sRX[e * 3 + 1] * f);
        atomicAdd(&g_dx[d_ * 3 + 2], sRX[e * 3 + 2] * f);
    }
}

// -------- node kernel: h_out = h + MLP([mi, h]); x_out = x + dx*mask --------
__global__ void __launch_bounds__(256, 2)
node_kernel(const float* __restrict__ h, const float* __restrict__ x,
            const float* __restrict__ mask,
            const float* __restrict__ bn1, const float* __restrict__ bn2,
            float* __restrict__ out, int N)
{
    extern __shared__ float sm[];
    float* zA = sm;                 // [TN][SA] : [mi | h]
    float* B1 = sm + TN * SA;       // [TN][SB] : u

    const int tid  = threadIdx.x;
    const int lane = tid & 31, wid = tid >> 5;
    const int mrow0 = (wid & 1) * 32, nq = wid >> 1;   // 2(M) x 4(N) warp grid
    const int g = lane >> 2, tig = lane & 3;
    const int n0 = blockIdx.x * TN;
    const int nN = min(TN, N - n0);

    #pragma unroll
    for (int it = 0; it < 8; it++) {
        const int e  = wid + it * 8;
        const int nd = n0 + min(e, nN - 1);
        const float4 vm = __ldg((const float4*)(g_mi + (size_t)nd * HID) + lane);
        const float4 vh = __ldg((const float4*)(h + (size_t)nd * HID) + lane);
        float4 w;
        w.x = to_tf32(vm.x); w.y = to_tf32(vm.y); w.z = to_tf32(vm.z); w.w = to_tf32(vm.w);
        *(float4*)(zA + e * SA + lane * 4) = w;
        w.x = to_tf32(vh.x); w.y = to_tf32(vh.y); w.z = to_tf32(vh.z); w.w = to_tf32(vh.w);
        *(float4*)(zA + e * SA + HID + lane * 4) = w;
    }
    __syncthreads();

    float acc[2][4][4];

    warp_gemm<NZK / 8>(zA, SA, g_wn1c, mrow0, nq, g, tig, lane, acc);
    epi_silu(B1, SB, bn1, mrow0, nq, g, tig, acc);
    __syncthreads();

    warp_gemm<HID / 8>(B1, SB, g_wn2c, mrow0, nq, g, tig, lane, acc);
    {
        #pragma unroll
        for (int mm = 0; mm < 2; mm++) {
            const int r0 = mrow0 + mm * 16 + g;
            #pragma unroll
            for (int na = 0; na < 4; na++) {
                const int c = nq * 32 + na * 8 + tig * 2;
                const float b0 = __ldg(bn2 + c), b1 = __ldg(bn2 + c + 1);
                if (r0 < nN) {
                    const size_t o = (size_t)(n0 + r0) * HID + c;
                    out[o]     = h[o]     + acc[mm][na][0] + b0;
                    out[o + 1] = h[o + 1] + acc[mm][na][1] + b1;
                }
                if (r0 + 8 < nN) {
                    const size_t o = (size_t)(n0 + r0 + 8) * HID + c;
                    out[o]     = h[o]     + acc[mm][na][2] + b0;
                    out[o + 1] = h[o + 1] + acc[mm][na][3] + b1;
                }
            }
        }
    }
    if (tid < nN) {
        const int nd = n0 + tid;
        const float m = mask[nd];
        const size_t xo = (size_t)N * HID;
        out[xo + nd * 3 + 0] = x[nd * 3 + 0] + g_dx[nd * 3 + 0] * m;
        out[xo + nd * 3 + 1] = x[nd * 3 + 1] + g_dx[nd * 3 + 1] * m;
        out[xo + nd * 3 + 2] = x[nd * 3 + 2] + g_dx[nd * 3 + 2] * m;
    }
}

extern "C" void kernel_launch(void* const* d_in, const int* in_sizes, int n_in,
                              void* d_out, int out_size) {
    const float* h    = (const float*)d_in[0];
    const float* x    = (const float*)d_in[1];
    const void*  ei   = d_in[2];
    const float* mask = (const float*)d_in[3];
    const float* ea   = (const float*)d_in[4];
    const float* We1  = (const float*)d_in[5];
    const float* be1  = (const float*)d_in[6];
    const float* We2  = (const float*)d_in[7];
    const float* be2  = (const float*)d_in[8];
    const float* Winf = (const float*)d_in[9];
    const float* binf = (const float*)d_in[10];
    const float* Wx1  = (const float*)d_in[11];
    const float* bx1  = (const float*)d_in[12];
    const float* Wx2  = (const float*)d_in[13];
    const float* Wn1  = (const float*)d_in[14];
    const float* bn1  = (const float*)d_in[15];
    const float* Wn2  = (const float*)d_in[16];
    const float* bn2  = (const float*)d_in[17];
    float* out = (float*)d_out;

    const int N = in_sizes[0] / HID;
    const int E = in_sizes[2] / 2;

    const int edge_smem = (TE * SA + TE * SB + TE * 8) * 4;   // ~221 KB
    const int node_smem = (TN * SA + TN * SB) * 4;            // ~106 KB

    cudaFuncSetAttribute(edge_kernel, cudaFuncAttributeMaxDynamicSharedMemorySize, edge_smem);
    cudaFuncSetAttribute(node_kernel, cudaFuncAttributeMaxDynamicSharedMemorySize, node_smem);

    init_kernel<<<2048, 256>>>((const int*)ei, We1, We2, Wx1, Wn1, Wn2, N);
    edge_kernel<<<(E + TE - 1) / TE, 512, edge_smem>>>(
        h, x, ei, ea, be1, be2, Winf, binf, bx1, Wx2, E);
    node_kernel<<<(N + TN - 1) / TN, 256, node_smem>>>(
        h, x, mask, bn1, bn2, out, N);
}

// round 11
// speedup vs baseline: 4.3542x; 1.1665x over previous
#include <cuda_runtime.h>

#define HID   128
#define EF    4
#define NG    20
#define FK    24       // feat k-dim (NG + EF), 3 k8-steps
#define TE    128      // edge tile
#define TN    64       // node tile
#define TP    128      // precompute tile
#define SF    36       // feat A-tile stride (conflict-free, 16B-aligned)
#define SB    132      // activation SMEM row stride
#define MAXN  50000

// -------- device scratch (no cudaMalloc allowed) --------
__device__ float g_mi[(size_t)MAXN * HID];
__device__ float g_dx[(size_t)MAXN * 3];
__device__ float g_u[(size_t)MAXN * HID];   // h @ We1[0:128]
__device__ float g_v[(size_t)MAXN * HID];   // h @ We1[128:256]
__device__ float g_p[(size_t)MAXN * HID];   // h @ Wn1[128:256]
__device__ int   g_idx64;
// fragment-packed tf32 weights (filled by init_kernel)
__device__ float g_wdp[HID * HID];    // We1 rows 0..127
__device__ float g_wsp[HID * HID];    // We1 rows 128..255
__device__ float g_w1f[FK * HID];     // We1 rows 256..279
__device__ float g_w2c[HID * HID];    // We2
__device__ float g_w3c[HID * HID];    // Wx1
__device__ float g_wn1m[HID * HID];   // Wn1 rows 0..127
__device__ float g_wnp[HID * HID];    // Wn1 rows 128..255
__device__ float g_wn2c[HID * HID];   // Wn2

// -------- helpers --------
__device__ __forceinline__ float to_tf32(float x) {
    float r; asm("cvt.rna.tf32.f32 %0, %1;" : "=f"(r) : "f"(x)); return r;
}
__device__ __forceinline__ float siluf(float v) {
    return __fdividef(v, 1.0f + __expf(-v));
}
__device__ __forceinline__ void mma8(float* d, const unsigned* a, const unsigned* b) {
    asm volatile(
        "mma.sync.aligned.m16n8k8.row.col.f32.tf32.tf32.f32 "
        "{%0,%1,%2,%3},{%4,%5,%6,%7},{%8,%9},{%0,%1,%2,%3};"
        : "+f"(d[0]), "+f"(d[1]), "+f"(d[2]), "+f"(d[3])
        : "r"(a[0]), "r"(a[1]), "r"(a[2]), "r"(a[3]), "r"(b[0]), "r"(b[1]));
}
__device__ __forceinline__ void red4(float* p, float a, float b, float c, float d) {
    asm volatile("red.global.add.v4.f32 [%0], {%1,%2,%3,%4};"
                 :: "l"(p), "f"(a), "f"(b), "f"(c), "f"(d) : "memory");
}

// -------- fragment packing (row_off selects weight sub-block) --------
// dst[(((k8*4+cg)*32+lane)*8) + na*2 + j] =
//   tf32( src[(row_off + k8*8 + tig + j*4)*HID + cg*32 + na*8 + g] )
__device__ __forceinline__ void pack_w(float* dst, const float* __restrict__ src,
                                       int i, int row_off) {
    const int j = i & 1, na = (i >> 1) & 3, lane = (i >> 3) & 31;
    const int cg = (i >> 8) & 3, k8 = i >> 10;
    const int tig = lane & 3, gg = lane >> 2;
    dst[i] = to_tf32(src[(row_off + k8 * 8 + tig + j * 4) * HID + cg * 32 + na * 8 + gg]);
}

// -------- warp GEMM with packed weights (32x32 warp tile, dist-2 prefetch) --------
template <int NK8>
__device__ __forceinline__ void warp_gemm(const float* __restrict__ As, int sa,
                                          const float* __restrict__ Wp,
                                          int mrow0, int nq, int g, int tig, int lane,
                                          float acc[2][4][4])
{
    #pragma unroll
    for (int mm = 0; mm < 2; mm++)
        #pragma unroll
        for (int na = 0; na < 4; na++)
            #pragma unroll
            for (int i = 0; i < 4; i++) acc[mm][na][i] = 0.0f;

    const float4* wp = (const float4*)Wp + ((size_t)nq * 32 + lane) * 2;
    const float*  a0 = As + (mrow0 + g) * sa + tig;
    float4 c0 = __ldg(wp + 0), c1 = __ldg(wp + 1);
    float4 n0 = c0, n1 = c1;
    if (NK8 > 1) { n0 = __ldg(wp + 256); n1 = __ldg(wp + 257); }

    #pragma unroll 2
    for (int k8 = 0; k8 < NK8; k8++) {
        const float4 f0 = c0, f1 = c1;
        c0 = n0; c1 = n1;
        if (k8 + 2 < NK8) {
            n0 = __ldg(wp + (size_t)(k8 + 2) * 256);
            n1 = __ldg(wp + (size_t)(k8 + 2) * 256 + 1);
        }
        unsigned bc[4][2] = {
            { __float_as_uint(f0.x), __float_as_uint(f0.y) },
            { __float_as_uint(f0.z), __float_as_uint(f0.w) },
            { __float_as_uint(f1.x), __float_as_uint(f1.y) },
            { __float_as_uint(f1.z), __float_as_uint(f1.w) } };
        unsigned a[2][4];
        const float* ak = a0 + k8 * 8;
        #pragma unroll
        for (int mm = 0; mm < 2; mm++) {
            const float* am = ak + mm * 16 * sa;
            a[mm][0] = __float_as_uint(am[0]);
            a[mm][1] = __float_as_uint(am[8 * sa]);
            a[mm][2] = __float_as_uint(am[4]);
            a[mm][3] = __float_as_uint(am[8 * sa + 4]);
        }
        #pragma unroll
        for (int mm = 0; mm < 2; mm++)
            #pragma unroll
            for (int na = 0; na < 4; na++)
                mma8(acc[mm][na], a[mm], bc[na]);
    }
}

// epilogue: dst[r][c] = tf32(silu(acc + bias[c]))
__device__ __forceinline__ void epi_silu(float* dst, int sd, const float* __restrict__ bias,
                                         int mrow0, int nq, int g, int tig, float acc[2][4][4])
{
    #pragma unroll
    for (int mm = 0; mm < 2; mm++) {
        const int r0 = mrow0 + mm * 16 + g;
        #pragma unroll
        for (int na = 0; na < 4; na++) {
            const int c = nq * 32 + na * 8 + tig * 2;
            const float b0 = __ldg(bias + c), b1 = __ldg(bias + c + 1);
            float2 v;
            v.x = to_tf32(siluf(acc[mm][na][0] + b0));
            v.y = to_tf32(siluf(acc[mm][na][1] + b1));
            *(float2*)(dst + r0 * sd + c) = v;
            v.x = to_tf32(siluf(acc[mm][na][2] + b0));
            v.y = to_tf32(siluf(acc[mm][na][3] + b1));
            *(float2*)(dst + (r0 + 8) * sd + c) = v;
        }
    }
}

// epilogue with SMEM additive term: dst = tf32(silu(acc + add[r][c] + bias[c]))
__device__ __forceinline__ void epi_silu_add(float* dst, int sd,
                                             const float* __restrict__ addb, int sadd,
                                             const float* __restrict__ bias,
                                             int mrow0, int nq, int g, int tig,
                                             float acc[2][4][4])
{
    #pragma unroll
    for (int mm = 0; mm < 2; mm++) {
        const int r0 = mrow0 + mm * 16 + g;
        #pragma unroll
        for (int na = 0; na < 4; na++) {
            const int c = nq * 32 + na * 8 + tig * 2;
            const float b0 = __ldg(bias + c), b1 = __ldg(bias + c + 1);
            const float2 u0 = *(const float2*)(addb + r0 * sadd + c);
            const float2 u1 = *(const float2*)(addb + (r0 + 8) * sadd + c);
            float2 v;
            v.x = to_tf32(siluf(acc[mm][na][0] + u0.x + b0));
            v.y = to_tf32(siluf(acc[mm][na][1] + u0.y + b1));
            *(float2*)(dst + r0 * sd + c) = v;
            v.x = to_tf32(siluf(acc[mm][na][2] + u1.x + b0));
            v.y = to_tf32(siluf(acc[mm][na][3] + u1.y + b1));
            *(float2*)(dst + (r0 + 8) * sd + c) = v;
        }
    }
}

// -------- init: zero accumulators, detect idx dtype, pack tf32 weights --------
__global__ void init_kernel(const int* __restrict__ ei32,
                            const float* __restrict__ We1, const float* __restrict__ We2,
                            const float* __restrict__ Wx1, const float* __restrict__ Wn1,
                            const float* __restrict__ Wn2, int N)
{
    if (blockIdx.x == 0 && threadIdx.x == 0) {
        int flag = 1;
        for (int i = 0; i < 64; i++)
            if (ei32[2 * i + 1] != 0) { flag = 0; break; }
        g_idx64 = flag;
    }
    const int nMi = N * HID, nDx = N * 3;
    const int nW = HID * HID, nWf = FK * HID;
    const int total = nMi + nDx + 7 * nW + nWf;
    for (int i = blockIdx.x * blockDim.x + threadIdx.x; i < total;
         i += gridDim.x * blockDim.x) {
        int j = i;
        if (j < nMi) { g_mi[j] = 0.0f; continue; }                  j -= nMi;
        if (j < nDx) { g_dx[j] = 0.0f; continue; }                  j -= nDx;
        if (j < nW)  { pack_w(g_wdp,  We1, j, 0);   continue; }     j -= nW;
        if (j < nW)  { pack_w(g_wsp,  We1, j, HID); continue; }     j -= nW;
        if (j < nWf) { pack_w(g_w1f,  We1, j, 2 * HID); continue; } j -= nWf;
        if (j < nW)  { pack_w(g_w2c,  We2, j, 0);   continue; }     j -= nW;
        if (j < nW)  { pack_w(g_w3c,  Wx1, j, 0);   continue; }     j -= nW;
        if (j < nW)  { pack_w(g_wn1m, Wn1, j, 0);   continue; }     j -= nW;
        if (j < nW)  { pack_w(g_wnp,  Wn1, j, HID); continue; }
        else         { pack_w(g_wn2c, Wn2, i - (total - nW), 0); }
    }
}

// -------- precompute: U = h@W_d, V = h@W_s, P = h@Wn1_h (per node) --------
__global__ void __launch_bounds__(512, 1)
pre_kernel(const float* __restrict__ h, int N)
{
    extern __shared__ float sm[];
    float* hA = sm;   // [TP][SB]

    const int tid  = threadIdx.x;
    const int lane = tid & 31, wid = tid >> 5;
    const int mrow0 = (wid & 3) * 32, nq = wid >> 2;
    const int g = lane >> 2, tig = lane & 3;
    const int n0 = blockIdx.x * TP;
    const int nN = min(TP, N - n0);

    #pragma unroll
    for (int it = 0; it < 8; it++) {
        const int r  = wid + it * 16;
        const int nd = n0 + min(r, nN - 1);
        const float4 vh = __ldg((const float4*)(h + (size_t)nd * HID) + lane);
        float4 w;
        w.x = to_tf32(vh.x); w.y = to_tf32(vh.y); w.z = to_tf32(vh.z); w.w = to_tf32(vh.w);
        *(float4*)(hA + r * SB + lane * 4) = w;
    }
    __syncthreads();

    float acc[2][4][4];
    const float* Wp[3] = { g_wdp, g_wsp, g_wnp };
    float* Gp[3];
    Gp[0] = g_u; Gp[1] = g_v; Gp[2] = g_p;

    #pragma unroll
    for (int m_ = 0; m_ < 3; m_++) {
        warp_gemm<HID / 8>(hA, SB, Wp[m_], mrow0, nq, g, tig, lane, acc);
        float* G = Gp[m_];
        #pragma unroll
        for (int mm = 0; mm < 2; mm++) {
            const int r0 = mrow0 + mm * 16 + g;
            #pragma unroll
            for (int na = 0; na < 4; na++) {
                const int c = nq * 32 + na * 8 + tig * 2;
                if (r0 < nN) {
                    float2 v; v.x = acc[mm][na][0]; v.y = acc[mm][na][1];
                    *(float2*)(G + (size_t)(n0 + r0) * HID + c) = v;
                }
                if (r0 + 8 < nN) {
                    float2 v; v.x = acc[mm][na][2]; v.y = acc[mm][na][3];
                    *(float2*)(G + (size_t)(n0 + r0 + 8) * HID + c) = v;
                }
            }
        }
    }
}

// -------- fused edge kernel: 128 edges/block, 512 threads --------
__global__ void __launch_bounds__(512, 1)
edge_kernel(const float* __restrict__ x,
            const void* __restrict__ eidx, const float* __restrict__ eattr,
            const float* __restrict__ be1, const float* __restrict__ be2,
            const float* __restrict__ Winf, const float* __restrict__ binf,
            const float* __restrict__ bx1, const float* __restrict__ Wx2, int E)
{
    extern __shared__ float sm[];
    float* FT   = sm;                       // [TE][SF] feat A-tile
    float* T1P  = sm + TE * SF;             // [TE][SB] U+V ; later MT (mij)
    float* B1   = T1P + TE * SB;            // [TE][SB] t1 ; later GT
    int*   sSrc = (int*)(B1 + TE * SB);
    int*   sDst = sSrc + TE;
    float* sD   = (float*)(sDst + TE);
    float* sRX  = sD + TE;                  // [TE][3]
    float* sEij = sRX + TE * 3;
    float* sXG  = sEij + TE;

    const int tid  = threadIdx.x;
    const int lane = tid & 31, wid = tid >> 5;
    const int mrow0 = (wid & 3) * 32, nq = wid >> 2;
    const int g = lane >> 2, tig = lane & 3;
    const long long ebase = (long long)blockIdx.x * TE;
    const int nE = (int)min((long long)TE, (long long)E - ebase);

    // ---- phase A: indices, geometry, gaussian feats, edge_attr ----
    if (tid < TE) {
        const int e = tid;
        const long long eg = ebase + min(e, nE - 1);
        int s_, d_;
        if (g_idx64) {
            const long long* p = (const long long*)eidx;
            s_ = (int)p[eg]; d_ = (int)p[(long long)E + eg];
        } else {
            const int* p = (const int*)eidx;
            s_ = p[eg]; d_ = p[(long long)E + eg];
        }
        sSrc[e] = s_; sDst[e] = d_;
        float rx = x[d_ * 3 + 0] - x[s_ * 3 + 0];
        float ry = x[d_ * 3 + 1] - x[s_ * 3 + 1];
        float rz = x[d_ * 3 + 2] - x[s_ * 3 + 2];
        float dd = sqrtf(rx * rx + ry * ry + rz * rz + 1e-8f);
        sD[e] = dd;
        sRX[e * 3 + 0] = rx; sRX[e * 3 + 1] = ry; sRX[e * 3 + 2] = rz;
        const float step  = 10.0f / 19.0f;
        const float coeff = -0.5f / (step * step);
        #pragma unroll
        for (int gg = 0; gg < NG; gg++) {
            float t = dd - step * (float)gg;
            FT[e * SF + gg] = to_tf32(__expf(coeff * t * t));
        }
        #pragma unroll
        for (int a_ = 0; a_ < EF; a_++)
            FT[e * SF + NG + a_] = to_tf32(eattr[eg * EF + a_]);
    }
    __syncthreads();

    // ---- gather U[dst] + V[src] -> T1P (fp32 additive term, coalesced) ----
    #pragma unroll
    for (int it = 0; it < 8; it++) {
        const int e = wid + it * 16;
        const float4 a = __ldg((const float4*)(g_u + (size_t)sDst[e] * HID) + lane);
        const float4 b = __ldg((const float4*)(g_v + (size_t)sSrc[e] * HID) + lane);
        float4 w;
        w.x = a.x + b.x; w.y = a.y + b.y; w.z = a.z + b.z; w.w = a.w + b.w;
        *(float4*)(T1P + e * SB + lane * 4) = w;
    }
    __syncthreads();

    float acc[2][4][4];

    // ---- GEMM1 (feat only, 3 k8): t1 = silu(feat@W_f + U+V + be1) -> B1 ----
    warp_gemm<FK / 8>(FT, SF, g_w1f, mrow0, nq, g, tig, lane, acc);
    epi_silu_add(B1, SB, T1P, SB, be1, mrow0, nq, g, tig, acc);
    __syncthreads();

    // ---- GEMM2: mij = silu(t1 @ We2 + be2) -> MT (overlays T1P) ----
    warp_gemm<HID / 8>(B1, SB, g_w2c, mrow0, nq, g, tig, lane, acc);
    float* MT = T1P;
    epi_silu(MT, SB, be2, mrow0, nq, g, tig, acc);
    __syncthreads();   // S1: MT visible

    // ---- eij = sigmoid(mij . Winf + binf) ----
    if (tid < TE) {
        float s = binf[0];
        #pragma unroll 4
        for (int k = 0; k < HID; k++)
            s += MT[tid * SB + k] * __ldg(&Winf[k]);
        sEij[tid] = __fdividef(1.0f, 1.0f + __expf(-s));
    }

    // ---- GEMM3: gx = silu(mij @ Wx1 + bx1) -> GT (overlays B1) ----
    warp_gemm<HID / 8>(MT, SB, g_w3c, mrow0, nq, g, tig, lane, acc);
    float* GT = B1;
    epi_silu(GT, SB, bx1, mrow0, nq, g, tig, acc);
    __syncthreads();   // S2: GT + sEij visible

    // ---- xg = tanh(gx . Wx2) ----
    if (tid < TE) {
        float s = 0.0f;
        #pragma unroll 4
        for (int k = 0; k < HID; k++)
            s += GT[tid * SB + k] * __ldg(&Wx2[k]);
        sXG[tid] = tanhf(s);
    }

    // ---- scatter: mi[dst] += mij*eij via red.global.add.v4.f32 ----
    #pragma unroll 2
    for (int i = 0; i < 8; i++) {
        const int e = wid * 8 + i;
        if (e < nE) {
            const float4 v = *(const float4*)(MT + e * SB + lane * 4);
            const float sc = sEij[e];
            red4(&g_mi[(size_t)sDst[e] * HID + lane * 4],
                 v.x * sc, v.y * sc, v.z * sc, v.w * sc);
        }
    }
    // ---- scatter: dx[dst] += rel_x/(d+1)*xg ----
    if (tid < nE) {
        const int e = tid, d_ = sDst[e];
        const float f = __fdividef(sXG[e], sD[e] + 1.0f);
        atomicAdd(&g_dx[d_ * 3 + 0], sRX[e * 3 + 0] * f);
        atomicAdd(&g_dx[d_ * 3 + 1], sRX[e * 3 + 1] * f);
        atomicAdd(&g_dx[d_ * 3 + 2], sRX[e * 3 + 2] * f);
    }
}

// -------- node kernel: h_out = h + MLP([mi, h]); x_out = x + dx*mask --------
__global__ void __launch_bounds__(256, 2)
node_kernel(const float* __restrict__ h, const float* __restrict__ x,
            const float* __restrict__ mask,
            const float* __restrict__ bn1, const float* __restrict__ bn2,
            float* __restrict__ out, int N)
{
    extern __shared__ float sm[];
    float* zA = sm;                 // [TN][SB] : mi (tf32)
    float* PB = sm + TN * SB;       // [TN][SB] : P = h@Wn1_h (fp32 additive)
    float* B1 = PB + TN * SB;       // [TN][SB] : u

    const int tid  = threadIdx.x;
    const int lane = tid & 31, wid = tid >> 5;
    const int mrow0 = (wid & 1) * 32, nq = wid >> 1;
    const int g = lane >> 2, tig = lane & 3;
    const int n0 = blockIdx.x * TN;
    const int nN = min(TN, N - n0);

    #pragma unroll
    for (int it = 0; it < 8; it++) {
        const int r  = wid + it * 8;
        const int nd = n0 + min(r, nN - 1);
        const float4 vm = __ldg((const float4*)(g_mi + (size_t)nd * HID) + lane);
        const float4 vp = __ldg((const float4*)(g_p + (size_t)nd * HID) + lane);
        float4 w;
        w.x = to_tf32(vm.x); w.y = to_tf32(vm.y); w.z = to_tf32(vm.z); w.w = to_tf32(vm.w);
        *(float4*)(zA + r * SB + lane * 4) = w;
        *(float4*)(PB + r * SB + lane * 4) = vp;
    }
    __syncthreads();

    float acc[2][4][4];

    // u = silu(mi@Wn1_mi + P + bn1)
    warp_gemm<HID / 8>(zA, SB, g_wn1m, mrow0, nq, g, tig, lane, acc);
    epi_silu_add(B1, SB, PB, SB, bn1, mrow0, nq, g, tig, acc);
    __syncthreads();

    warp_gemm<HID / 8>(B1, SB, g_wn2c, mrow0, nq, g, tig, lane, acc);
    {
        #pragma unroll
        for (int mm = 0; mm < 2; mm++) {
            const int r0 = mrow0 + mm * 16 + g;
            #pragma unroll
            for (int na = 0; na < 4; na++) {
                const int c = nq * 32 + na * 8 + tig * 2;
                const float b0 = __ldg(bn2 + c), b1 = __ldg(bn2 + c + 1);
                if (r0 < nN) {
                    const size_t o = (size_t)(n0 + r0) * HID + c;
                    out[o]     = h[o]     + acc[mm][na][0] + b0;
                    out[o + 1] = h[o + 1] + acc[mm][na][1] + b1;
                }
                if (r0 + 8 < nN) {
                    const size_t o = (size_t)(n0 + r0 + 8) * HID + c;
                    out[o]     = h[o]     + acc[mm][na][2] + b0;
                    out[o + 1] = h[o + 1] + acc[mm][na][3] + b1;
                }
            }
        }
    }
    if (tid < nN) {
        const int nd = n0 + tid;
        const float m = mask[nd];
        const size_t xo = (size_t)N * HID;
        out[xo + nd * 3 + 0] = x[nd * 3 + 0] + g_dx[nd * 3 + 0] * m;
        out[xo + nd * 3 + 1] = x[nd * 3 + 1] + g_dx[nd * 3 + 1] * m;
        out[xo + nd * 3 + 2] = x[nd * 3 + 2] + g_dx[nd * 3 + 2] * m;
    }
}

extern "C" void kernel_launch(void* const* d_in, const int* in_sizes, int n_in,
                              void* d_out, int out_size) {
    const float* h    = (const float*)d_in[0];
    const float* x    = (const float*)d_in[1];
    const void*  ei   = d_in[2];
    const float* mask = (const float*)d_in[3];
    const float* ea   = (const float*)d_in[4];
    const float* We1  = (const float*)d_in[5];
    const float* be1  = (const float*)d_in[6];
    const float* We2  = (const float*)d_in[7];
    const float* be2  = (const float*)d_in[8];
    const float* Winf = (const float*)d_in[9];
    const float* binf = (const float*)d_in[10];
    const float* Wx1  = (const float*)d_in[11];
    const float* bx1  = (const float*)d_in[12];
    const float* Wx2  = (const float*)d_in[13];
    const float* Wn1  = (const float*)d_in[14];
    const float* bn1  = (const float*)d_in[15];
    const float* Wn2  = (const float*)d_in[16];
    const float* bn2  = (const float*)d_in[17];
    float* out = (float*)d_out;

    const int N = in_sizes[0] / HID;
    const int E = in_sizes[2] / 2;

    const int pre_smem  = TP * SB * 4;                               // ~67.6 KB
    const int edge_smem = (TE * SF + 2 * TE * SB + TE * 8) * 4;      // ~157.7 KB
    const int node_smem = 3 * TN * SB * 4;                           // ~101.4 KB

    cudaFuncSetAttribute(pre_kernel,  cudaFuncAttributeMaxDynamicSharedMemorySize, pre_smem);
    cudaFuncSetAttribute(edge_kernel, cudaFuncAttributeMaxDynamicSharedMemorySize, edge_smem);
    cudaFuncSetAttribute(node_kernel, cudaFuncAttributeMaxDynamicSharedMemorySize, node_smem);

    init_kernel<<<2048, 256>>>((const int*)ei, We1, We2, Wx1, Wn1, Wn2, N);
    pre_kernel<<<(N + TP - 1) / TP, 512, pre_smem>>>(h, N);
    edge_kernel<<<(E + TE - 1) / TE, 512, edge_smem>>>(
        x, ei, ea, be1, be2, Winf, binf, bx1, Wx2, E);
    node_kernel<<<(N + TN - 1) / TN, 256, node_smem>>>(
        h, x, mask, bn1, bn2, out, N);
}

// round 12
// speedup vs baseline: 4.5059x; 1.0348x over previous
#include <cuda_runtime.h>

#define HID   128
#define EF    4
#define NG    20
#define FK    24       // feat k-dim (NG + EF), 3 k8-steps
#define TE    64       // edge tile (2 blocks/SM co-resident)
#define TN    64       // node tile
#define TP    128      // precompute tile
#define SF    36       // feat A-tile stride (conflict-free, 16B-aligned)
#define SB    132      // activation SMEM row stride
#define MAXN  50000

// -------- device scratch (no cudaMalloc allowed) --------
__device__ float g_mi[(size_t)MAXN * HID];
__device__ float g_dx[(size_t)MAXN * 3];
__device__ float g_u[(size_t)MAXN * HID];   // h @ We1[0:128]
__device__ float g_v[(size_t)MAXN * HID];   // h @ We1[128:256]
__device__ float g_p[(size_t)MAXN * HID];   // h @ Wn1[128:256]
__device__ int   g_idx64;
// fragment-packed tf32 weights (filled by init_kernel)
__device__ float g_wdp[HID * HID];    // We1 rows 0..127
__device__ float g_wsp[HID * HID];    // We1 rows 128..255
__device__ float g_w1f[FK * HID];     // We1 rows 256..279
__device__ float g_w2c[HID * HID];    // We2
__device__ float g_w3c[HID * HID];    // Wx1
__device__ float g_wn1m[HID * HID];   // Wn1 rows 0..127
__device__ float g_wnp[HID * HID];    // Wn1 rows 128..255
__device__ float g_wn2c[HID * HID];   // Wn2

// -------- helpers --------
__device__ __forceinline__ float to_tf32(float x) {
    float r; asm("cvt.rna.tf32.f32 %0, %1;" : "=f"(r) : "f"(x)); return r;
}
__device__ __forceinline__ float siluf(float v) {
    return __fdividef(v, 1.0f + __expf(-v));
}
__device__ __forceinline__ void mma8(float* d, const unsigned* a, const unsigned* b) {
    asm volatile(
        "mma.sync.aligned.m16n8k8.row.col.f32.tf32.tf32.f32 "
        "{%0,%1,%2,%3},{%4,%5,%6,%7},{%8,%9},{%0,%1,%2,%3};"
        : "+f"(d[0]), "+f"(d[1]), "+f"(d[2]), "+f"(d[3])
        : "r"(a[0]), "r"(a[1]), "r"(a[2]), "r"(a[3]), "r"(b[0]), "r"(b[1]));
}
__device__ __forceinline__ void red4(float* p, float a, float b, float c, float d) {
    asm volatile("red.global.add.v4.f32 [%0], {%1,%2,%3,%4};"
                 :: "l"(p), "f"(a), "f"(b), "f"(c), "f"(d) : "memory");
}

// -------- fragment packing (row_off selects weight sub-block) --------
__device__ __forceinline__ void pack_w(float* dst, const float* __restrict__ src,
                                       int i, int row_off) {
    const int j = i & 1, na = (i >> 1) & 3, lane = (i >> 3) & 31;
    const int cg = (i >> 8) & 3, k8 = i >> 10;
    const int tig = lane & 3, gg = lane >> 2;
    dst[i] = to_tf32(src[(row_off + k8 * 8 + tig + j * 4) * HID + cg * 32 + na * 8 + gg]);
}

// -------- warp GEMM with packed weights (32x32 warp tile, dist-2 prefetch) --------
template <int NK8>
__device__ __forceinline__ void warp_gemm(const float* __restrict__ As, int sa,
                                          const float* __restrict__ Wp,
                                          int mrow0, int nq, int g, int tig, int lane,
                                          float acc[2][4][4])
{
    #pragma unroll
    for (int mm = 0; mm < 2; mm++)
        #pragma unroll
        for (int na = 0; na < 4; na++)
            #pragma unroll
            for (int i = 0; i < 4; i++) acc[mm][na][i] = 0.0f;

    const float4* wp = (const float4*)Wp + ((size_t)nq * 32 + lane) * 2;
    const float*  a0 = As + (mrow0 + g) * sa + tig;
    float4 c0 = __ldg(wp + 0), c1 = __ldg(wp + 1);
    float4 n0 = c0, n1 = c1;
    if (NK8 > 1) { n0 = __ldg(wp + 256); n1 = __ldg(wp + 257); }

    #pragma unroll 2
    for (int k8 = 0; k8 < NK8; k8++) {
        const float4 f0 = c0, f1 = c1;
        c0 = n0; c1 = n1;
        if (k8 + 2 < NK8) {
            n0 = __ldg(wp + (size_t)(k8 + 2) * 256);
            n1 = __ldg(wp + (size_t)(k8 + 2) * 256 + 1);
        }
        unsigned bc[4][2] = {
            { __float_as_uint(f0.x), __float_as_uint(f0.y) },
            { __float_as_uint(f0.z), __float_as_uint(f0.w) },
            { __float_as_uint(f1.x), __float_as_uint(f1.y) },
            { __float_as_uint(f1.z), __float_as_uint(f1.w) } };
        unsigned a[2][4];
        const float* ak = a0 + k8 * 8;
        #pragma unroll
        for (int mm = 0; mm < 2; mm++) {
            const float* am = ak + mm * 16 * sa;
            a[mm][0] = __float_as_uint(am[0]);
            a[mm][1] = __float_as_uint(am[8 * sa]);
            a[mm][2] = __float_as_uint(am[4]);
            a[mm][3] = __float_as_uint(am[8 * sa + 4]);
        }
        #pragma unroll
        for (int mm = 0; mm < 2; mm++)
            #pragma unroll
            for (int na = 0; na < 4; na++)
                mma8(acc[mm][na], a[mm], bc[na]);
    }
}

// epilogue: dst[r][c] = tf32(silu(acc + bias[c]))
__device__ __forceinline__ void epi_silu(float* dst, int sd, const float* __restrict__ bias,
                                         int mrow0, int nq, int g, int tig, float acc[2][4][4])
{
    #pragma unroll
    for (int mm = 0; mm < 2; mm++) {
        const int r0 = mrow0 + mm * 16 + g;
        #pragma unroll
        for (int na = 0; na < 4; na++) {
            const int c = nq * 32 + na * 8 + tig * 2;
            const float b0 = __ldg(bias + c), b1 = __ldg(bias + c + 1);
            float2 v;
            v.x = to_tf32(siluf(acc[mm][na][0] + b0));
            v.y = to_tf32(siluf(acc[mm][na][1] + b1));
            *(float2*)(dst + r0 * sd + c) = v;
            v.x = to_tf32(siluf(acc[mm][na][2] + b0));
            v.y = to_tf32(siluf(acc[mm][na][3] + b1));
            *(float2*)(dst + (r0 + 8) * sd + c) = v;
        }
    }
}

// epilogue with SMEM additive term: dst = tf32(silu(acc + add[r][c] + bias[c]))
__device__ __forceinline__ void epi_silu_add(float* dst, int sd,
                                             const float* __restrict__ addb, int sadd,
                                             const float* __restrict__ bias,
                                             int mrow0, int nq, int g, int tig,
                                             float acc[2][4][4])
{
    #pragma unroll
    for (int mm = 0; mm < 2; mm++) {
        const int r0 = mrow0 + mm * 16 + g;
        #pragma unroll
        for (int na = 0; na < 4; na++) {
            const int c = nq * 32 + na * 8 + tig * 2;
            const float b0 = __ldg(bias + c), b1 = __ldg(bias + c + 1);
            const float2 u0 = *(const float2*)(addb + r0 * sadd + c);
            const float2 u1 = *(const float2*)(addb + (r0 + 8) * sadd + c);
            float2 v;
            v.x = to_tf32(siluf(acc[mm][na][0] + u0.x + b0));
            v.y = to_tf32(siluf(acc[mm][na][1] + u0.y + b1));
            *(float2*)(dst + r0 * sd + c) = v;
            v.x = to_tf32(siluf(acc[mm][na][2] + u1.x + b0));
            v.y = to_tf32(siluf(acc[mm][na][3] + u1.y + b1));
            *(float2*)(dst + (r0 + 8) * sd + c) = v;
        }
    }
}

// -------- init: zero accumulators, detect idx dtype, pack tf32 weights --------
__global__ void init_kernel(const int* __restrict__ ei32,
                            const float* __restrict__ We1, const float* __restrict__ We2,
                            const float* __restrict__ Wx1, const float* __restrict__ Wn1,
                            const float* __restrict__ Wn2, int N)
{
    if (blockIdx.x == 0 && threadIdx.x == 0) {
        int flag = 1;
        for (int i = 0; i < 64; i++)
            if (ei32[2 * i + 1] != 0) { flag = 0; break; }
        g_idx64 = flag;
    }
    const int nMi = N * HID, nDx = N * 3;
    const int nW = HID * HID, nWf = FK * HID;
    const int total = nMi + nDx + 7 * nW + nWf;
    for (int i = blockIdx.x * blockDim.x + threadIdx.x; i < total;
         i += gridDim.x * blockDim.x) {
        int j = i;
        if (j < nMi) { g_mi[j] = 0.0f; continue; }                  j -= nMi;
        if (j < nDx) { g_dx[j] = 0.0f; continue; }                  j -= nDx;
        if (j < nW)  { pack_w(g_wdp,  We1, j, 0);   continue; }     j -= nW;
        if (j < nW)  { pack_w(g_wsp,  We1, j, HID); continue; }     j -= nW;
        if (j < nWf) { pack_w(g_w1f,  We1, j, 2 * HID); continue; } j -= nWf;
        if (j < nW)  { pack_w(g_w2c,  We2, j, 0);   continue; }     j -= nW;
        if (j < nW)  { pack_w(g_w3c,  Wx1, j, 0);   continue; }     j -= nW;
        if (j < nW)  { pack_w(g_wn1m, Wn1, j, 0);   continue; }     j -= nW;
        if (j < nW)  { pack_w(g_wnp,  Wn1, j, HID); continue; }
        else         { pack_w(g_wn2c, Wn2, i - (total - nW), 0); }
    }
}

// -------- precompute: U = h@W_d, V = h@W_s, P = h@Wn1_h (per node) --------
__global__ void __launch_bounds__(512, 1)
pre_kernel(const float* __restrict__ h, int N)
{
    extern __shared__ float sm[];
    float* hA = sm;   // [TP][SB]

    const int tid  = threadIdx.x;
    const int lane = tid & 31, wid = tid >> 5;
    const int mrow0 = (wid & 3) * 32, nq = wid >> 2;
    const int g = lane >> 2, tig = lane & 3;
    const int n0 = blockIdx.x * TP;
    const int nN = min(TP, N - n0);

    #pragma unroll
    for (int it = 0; it < 8; it++) {
        const int r  = wid + it * 16;
        const int nd = n0 + min(r, nN - 1);
        const float4 vh = __ldg((const float4*)(h + (size_t)nd * HID) + lane);
        float4 w;
        w.x = to_tf32(vh.x); w.y = to_tf32(vh.y); w.z = to_tf32(vh.z); w.w = to_tf32(vh.w);
        *(float4*)(hA + r * SB + lane * 4) = w;
    }
    __syncthreads();

    float acc[2][4][4];
    const float* Wp[3] = { g_wdp, g_wsp, g_wnp };
    float* Gp[3];
    Gp[0] = g_u; Gp[1] = g_v; Gp[2] = g_p;

    #pragma unroll
    for (int m_ = 0; m_ < 3; m_++) {
        warp_gemm<HID / 8>(hA, SB, Wp[m_], mrow0, nq, g, tig, lane, acc);
        float* G = Gp[m_];
        #pragma unroll
        for (int mm = 0; mm < 2; mm++) {
            const int r0 = mrow0 + mm * 16 + g;
            #pragma unroll
            for (int na = 0; na < 4; na++) {
                const int c = nq * 32 + na * 8 + tig * 2;
                if (r0 < nN) {
                    float2 v; v.x = acc[mm][na][0]; v.y = acc[mm][na][1];
                    *(float2*)(G + (size_t)(n0 + r0) * HID + c) = v;
                }
                if (r0 + 8 < nN) {
                    float2 v; v.x = acc[mm][na][2]; v.y = acc[mm][na][3];
                    *(float2*)(G + (size_t)(n0 + r0 + 8) * HID + c) = v;
                }
            }
        }
    }
}

// -------- fused edge kernel: 64 edges/block, 256 threads, 2 blocks/SM --------
__global__ void __launch_bounds__(256, 2)
edge_kernel(const float* __restrict__ x,
            const void* __restrict__ eidx, const float* __restrict__ eattr,
            const float* __restrict__ be1, const float* __restrict__ be2,
            const float* __restrict__ Winf, const float* __restrict__ binf,
            const float* __restrict__ bx1, const float* __restrict__ Wx2, int E)
{
    extern __shared__ float sm[];
    float* FT   = sm;                       // [TE][SF] feat A-tile
    float* T1P  = sm + TE * SF;             // [TE][SB] U+V ; later MT (mij)
    float* B1   = T1P + TE * SB;            // [TE][SB] t1 ; later GT
    int*   sSrc = (int*)(B1 + TE * SB);
    int*   sDst = sSrc + TE;
    float* sD   = (float*)(sDst + TE);
    float* sRX  = sD + TE;                  // [TE][3]
    float* sEij = sRX + TE * 3;
    float* sXG  = sEij + TE;

    const int tid  = threadIdx.x;
    const int lane = tid & 31, wid = tid >> 5;
    const int mrow0 = (wid & 1) * 32, nq = wid >> 1;   // 2(M) x 4(N) warp grid
    const int g = lane >> 2, tig = lane & 3;
    const long long ebase = (long long)blockIdx.x * TE;
    const int nE = (int)min((long long)TE, (long long)E - ebase);

    // ---- phase A: indices, geometry, gaussian feats, edge_attr ----
    if (tid < TE) {
        const int e = tid;
        const long long eg = ebase + min(e, nE - 1);
        int s_, d_;
        if (g_idx64) {
            const long long* p = (const long long*)eidx;
            s_ = (int)p[eg]; d_ = (int)p[(long long)E + eg];
        } else {
            const int* p = (const int*)eidx;
            s_ = p[eg]; d_ = p[(long long)E + eg];
        }
        sSrc[e] = s_; sDst[e] = d_;
        float rx = x[d_ * 3 + 0] - x[s_ * 3 + 0];
        float ry = x[d_ * 3 + 1] - x[s_ * 3 + 1];
        float rz = x[d_ * 3 + 2] - x[s_ * 3 + 2];
        float dd = sqrtf(rx * rx + ry * ry + rz * rz + 1e-8f);
        sD[e] = dd;
        sRX[e * 3 + 0] = rx; sRX[e * 3 + 1] = ry; sRX[e * 3 + 2] = rz;
        const float step  = 10.0f / 19.0f;
        const float coeff = -0.5f / (step * step);
        #pragma unroll
        for (int gg = 0; gg < NG; gg++) {
            float t = dd - step * (float)gg;
            FT[e * SF + gg] = to_tf32(__expf(coeff * t * t));
        }
        #pragma unroll
        for (int a_ = 0; a_ < EF; a_++)
            FT[e * SF + NG + a_] = to_tf32(eattr[eg * EF + a_]);
    }
    __syncthreads();

    // ---- gather U[dst] + V[src] -> T1P (fp32 additive term, coalesced) ----
    #pragma unroll
    for (int it = 0; it < 8; it++) {
        const int e = wid + it * 8;
        const float4 a = __ldg((const float4*)(g_u + (size_t)sDst[e] * HID) + lane);
        const float4 b = __ldg((const float4*)(g_v + (size_t)sSrc[e] * HID) + lane);
        float4 w;
        w.x = a.x + b.x; w.y = a.y + b.y; w.z = a.z + b.z; w.w = a.w + b.w;
        *(float4*)(T1P + e * SB + lane * 4) = w;
    }
    __syncthreads();

    float acc[2][4][4];

    // ---- GEMM1 (feat only, 3 k8): t1 = silu(feat@W_f + U+V + be1) -> B1 ----
    warp_gemm<FK / 8>(FT, SF, g_w1f, mrow0, nq, g, tig, lane, acc);
    epi_silu_add(B1, SB, T1P, SB, be1, mrow0, nq, g, tig, acc);
    __syncthreads();

    // ---- GEMM2: mij = silu(t1 @ We2 + be2) -> MT (overlays T1P) ----
    warp_gemm<HID / 8>(B1, SB, g_w2c, mrow0, nq, g, tig, lane, acc);
    float* MT = T1P;
    epi_silu(MT, SB, be2, mrow0, nq, g, tig, acc);
    __syncthreads();   // S1: MT visible

    // ---- eij = sigmoid(mij . Winf + binf) ----
    if (tid < TE) {
        float s = binf[0];
        #pragma unroll 4
        for (int k = 0; k < HID; k++)
            s += MT[tid * SB + k] * __ldg(&Winf[k]);
        sEij[tid] = __fdividef(1.0f, 1.0f + __expf(-s));
    }

    // ---- GEMM3: gx = silu(mij @ Wx1 + bx1) -> GT (overlays B1) ----
    warp_gemm<HID / 8>(MT, SB, g_w3c, mrow0, nq, g, tig, lane, acc);
    float* GT = B1;
    epi_silu(GT, SB, bx1, mrow0, nq, g, tig, acc);
    __syncthreads();   // S2: GT + sEij visible

    // ---- xg = tanh(gx . Wx2) ----
    if (tid < TE) {
        float s = 0.0f;
        #pragma unroll 4
        for (int k = 0; k < HID; k++)
            s += GT[tid * SB + k] * __ldg(&Wx2[k]);
        sXG[tid] = tanhf(s);
    }

    // ---- scatter: mi[dst] += mij*eij via red.global.add.v4.f32 ----
    #pragma unroll 2
    for (int i = 0; i < 8; i++) {
        const int e = wid * 8 + i;
        if (e < nE) {
            const float4 v = *(const float4*)(MT + e * SB + lane * 4);
            const float sc = sEij[e];
            red4(&g_mi[(size_t)sDst[e] * HID + lane * 4],
                 v.x * sc, v.y * sc, v.z * sc, v.w * sc);
        }
    }
    // ---- scatter: dx[dst] += rel_x/(d+1)*xg ----
    if (tid < nE) {
        const int e = tid, d_ = sDst[e];
        const float f = __fdividef(sXG[e], sD[e] + 1.0f);
        atomicAdd(&g_dx[d_ * 3 + 0], sRX[e * 3 + 0] * f);
        atomicAdd(&g_dx[d_ * 3 + 1], sRX[e * 3 + 1] * f);
        atomicAdd(&g_dx[d_ * 3 + 2], sRX[e * 3 + 2] * f);
    }
}

// -------- node kernel: h_out = h + MLP([mi, h]); x_out = x + dx*mask --------
__global__ void __launch_bounds__(256, 2)
node_kernel(const float* __restrict__ h, const float* __restrict__ x,
            const float* __restrict__ mask,
            const float* __restrict__ bn1, const float* __restrict__ bn2,
            float* __restrict__ out, int N)
{
    extern __shared__ float sm[];
    float* zA = sm;                 // [TN][SB] : mi (tf32)
    float* PB = sm + TN * SB;       // [TN][SB] : P = h@Wn1_h (fp32 additive)
    float* B1 = PB + TN * SB;       // [TN][SB] : u

    const int tid  = threadIdx.x;
    const int lane = tid & 31, wid = tid >> 5;
    const int mrow0 = (wid & 1) * 32, nq = wid >> 1;
    const int g = lane >> 2, tig = lane & 3;
    const int n0 = blockIdx.x * TN;
    const int nN = min(TN, N - n0);

    #pragma unroll
    for (int it = 0; it < 8; it++) {
        const int r  = wid + it * 8;
        const int nd = n0 + min(r, nN - 1);
        const float4 vm = __ldg((const float4*)(g_mi + (size_t)nd * HID) + lane);
        const float4 vp = __ldg((const float4*)(g_p + (size_t)nd * HID) + lane);
        float4 w;
        w.x = to_tf32(vm.x); w.y = to_tf32(vm.y); w.z = to_tf32(vm.z); w.w = to_tf32(vm.w);
        *(float4*)(zA + r * SB + lane * 4) = w;
        *(float4*)(PB + r * SB + lane * 4) = vp;
    }
    __syncthreads();

    float acc[2][4][4];

    // u = silu(mi@Wn1_mi + P + bn1)
    warp_gemm<HID / 8>(zA, SB, g_wn1m, mrow0, nq, g, tig, lane, acc);
    epi_silu_add(B1, SB, PB, SB, bn1, mrow0, nq, g, tig, acc);
    __syncthreads();

    warp_gemm<HID / 8>(B1, SB, g_wn2c, mrow0, nq, g, tig, lane, acc);
    {
        #pragma unroll
        for (int mm = 0; mm < 2; mm++) {
            const int r0 = mrow0 + mm * 16 + g;
            #pragma unroll
            for (int na = 0; na < 4; na++) {
                const int c = nq * 32 + na * 8 + tig * 2;
                const float b0 = __ldg(bn2 + c), b1 = __ldg(bn2 + c + 1);
                if (r0 < nN) {
                    const size_t o = (size_t)(n0 + r0) * HID + c;
                    out[o]     = h[o]     + acc[mm][na][0] + b0;
                    out[o + 1] = h[o + 1] + acc[mm][na][1] + b1;
                }
                if (r0 + 8 < nN) {
                    const size_t o = (size_t)(n0 + r0 + 8) * HID + c;
                    out[o]     = h[o]     + acc[mm][na][2] + b0;
                    out[o + 1] = h[o + 1] + acc[mm][na][3] + b1;
                }
            }
        }
    }
    if (tid < nN) {
        const int nd = n0 + tid;
        const float m = mask[nd];
        const size_t xo = (size_t)N * HID;
        out[xo + nd * 3 + 0] = x[nd * 3 + 0] + g_dx[nd * 3 + 0] * m;
        out[xo + nd * 3 + 1] = x[nd * 3 + 1] + g_dx[nd * 3 + 1] * m;
        out[xo + nd * 3 + 2] = x[nd * 3 + 2] + g_dx[nd * 3 + 2] * m;
    }
}

extern "C" void kernel_launch(void* const* d_in, const int* in_sizes, int n_in,
                              void* d_out, int out_size) {
    const float* h    = (const float*)d_in[0];
    const float* x    = (const float*)d_in[1];
    const void*  ei   = d_in[2];
    const float* mask = (const float*)d_in[3];
    const float* ea   = (const float*)d_in[4];
    const float* We1  = (const float*)d_in[5];
    const float* be1  = (const float*)d_in[6];
    const float* We2  = (const float*)d_in[7];
    const float* be2  = (const float*)d_in[8];
    const float* Winf = (const float*)d_in[9];
    const float* binf = (const float*)d_in[10];
    const float* Wx1  = (const float*)d_in[11];
    const float* bx1  = (const float*)d_in[12];
    const float* Wx2  = (const float*)d_in[13];
    const float* Wn1  = (const float*)d_in[14];
    const float* bn1  = (const float*)d_in[15];
    const float* Wn2  = (const float*)d_in[16];
    const float* bn2  = (const float*)d_in[17];
    float* out = (float*)d_out;

    const int N = in_sizes[0] / HID;
    const int E = in_sizes[2] / 2;

    const int pre_smem  = TP * SB * 4;                               // ~67.6 KB
    const int edge_smem = (TE * SF + 2 * TE * SB + TE * 8) * 4;      // ~78.8 KB
    const int node_smem = 3 * TN * SB * 4;                           // ~101.4 KB

    cudaFuncSetAttribute(pre_kernel,  cudaFuncAttributeMaxDynamicSharedMemorySize, pre_smem);
    cudaFuncSetAttribute(edge_kernel, cudaFuncAttributeMaxDynamicSharedMemorySize, edge_smem);
    cudaFuncSetAttribute(node_kernel, cudaFuncAttributeMaxDynamicSharedMemorySize, node_smem);

    init_kernel<<<2048, 256>>>((const int*)ei, We1, We2, Wx1, Wn1, Wn2, N);
    pre_kernel<<<(N + TP - 1) / TP, 512, pre_smem>>>(h, N);
    edge_kernel<<<(E + TE - 1) / TE, 256, edge_smem>>>(
        x, ei, ea, be1, be2, Winf, binf, bx1, Wx2, E);
    node_kernel<<<(N + TN - 1) / TN, 256, node_smem>>>(
        h, x, mask, bn1, bn2, out, N);
}

// round 14
// speedup vs baseline: 4.9061x; 1.0888x over previous
#include <cuda_runtime.h>
#include <cuda_bf16.h>
#include <cstdint>

#define HID   128
#define EF    4
#define NG    20
#define FK    24       // feat k-dim (NG + EF), 3 k8-steps
#define TE    64       // edge tile (2 blocks/SM co-resident)
#define TN    64       // node tile
#define TP    128      // precompute tile
#define SF    36       // feat A-tile stride (conflict-free, 16B-aligned)
#define SB    132      // activation SMEM row stride (fp32)
#define SH    136      // bf16 mij tile stride (bf16 elems; 272B, conflict-free)
#define MAXN  50000

// -------- device scratch (no cudaMalloc allowed) --------
__device__ float g_mi[(size_t)MAXN * HID];
__device__ float g_dx[(size_t)MAXN * 3];
__device__ float g_u[(size_t)MAXN * HID];   // h @ We1[0:128]
__device__ float g_v[(size_t)MAXN * HID];   // h @ We1[128:256]
__device__ float g_p[(size_t)MAXN * HID];   // h @ Wn1[128:256]
__device__ int   g_idx64;
// fragment-packed tf32 weights
__device__ float g_wdp[HID * HID];    // We1 rows 0..127
__device__ float g_wsp[HID * HID];    // We1 rows 128..255
__device__ float g_w1f[FK * HID];     // We1 rows 256..279
__device__ float g_w2c[HID * HID];    // We2
__device__ float g_wn1m[HID * HID];   // Wn1 rows 0..127
__device__ float g_wnp[HID * HID];    // Wn1 rows 128..255
__device__ float g_wn2c[HID * HID];   // Wn2
// fragment-packed bf16 weights for GEMM3 (m16n8k16): HID*HID/2 words
__device__ uint32_t g_wx1h[HID * HID / 2];

// -------- helpers --------
__device__ __forceinline__ float to_tf32(float x) {
    float r; asm("cvt.rna.tf32.f32 %0, %1;" : "=f"(r) : "f"(x)); return r;
}
__device__ __forceinline__ float siluf(float v) {
    return __fdividef(v, 1.0f + __expf(-v));
}
__device__ __forceinline__ void mma8(float* d, const unsigned* a, const unsigned* b) {
    asm volatile(
        "mma.sync.aligned.m16n8k8.row.col.f32.tf32.tf32.f32 "
        "{%0,%1,%2,%3},{%4,%5,%6,%7},{%8,%9},{%0,%1,%2,%3};"
        : "+f"(d[0]), "+f"(d[1]), "+f"(d[2]), "+f"(d[3])
        : "r"(a[0]), "r"(a[1]), "r"(a[2]), "r"(a[3]), "r"(b[0]), "r"(b[1]));
}
__device__ __forceinline__ void mma16(float* d, const unsigned* a, const unsigned* b) {
    asm volatile(
        "mma.sync.aligned.m16n8k16.row.col.f32.bf16.bf16.f32 "
        "{%0,%1,%2,%3},{%4,%5,%6,%7},{%8,%9},{%0,%1,%2,%3};"
        : "+f"(d[0]), "+f"(d[1]), "+f"(d[2]), "+f"(d[3])
        : "r"(a[0]), "r"(a[1]), "r"(a[2]), "r"(a[3]), "r"(b[0]), "r"(b[1]));
}
__device__ __forceinline__ void red4(float* p, float a, float b, float c, float d) {
    asm volatile("red.global.add.v4.f32 [%0], {%1,%2,%3,%4};"
                 :: "l"(p), "f"(a), "f"(b), "f"(c), "f"(d) : "memory");
}

// -------- tf32 fragment packing (row_off selects weight sub-block) --------
__device__ __forceinline__ void pack_w(float* dst, const float* __restrict__ src,
                                       int i, int row_off) {
    const int j = i & 1, na = (i >> 1) & 3, lane = (i >> 3) & 31;
    const int cg = (i >> 8) & 3, k8 = i >> 10;
    const int tig = lane & 3, gg = lane >> 2;
    dst[i] = to_tf32(src[(row_off + k8 * 8 + tig + j * 4) * HID + cg * 32 + na * 8 + gg]);
}
// -------- bf16 fragment packing (m16n8k16 B-operand), i = word index --------
// word[(((k16*4+cg)*32+lane)*8) + na*2 + j] = bf16x2( src[r0][c], src[r0+1][c] )
//   r0 = k16*16 + j*8 + 2*tig,  c = cg*32 + na*8 + g
__device__ __forceinline__ void pack_wh(uint32_t* dst, const float* __restrict__ src, int i) {
    const int j = i & 1, na = (i >> 1) & 3, lane = (i >> 3) & 31;
    const int cg = (i >> 8) & 3, k16 = i >> 10;
    const int tig = lane & 3, gg = lane >> 2;
    const int r0 = k16 * 16 + j * 8 + 2 * tig;
    const int c  = cg * 32 + na * 8 + gg;
    __nv_bfloat162 h2 = __floats2bfloat162_rn(src[r0 * HID + c], src[(r0 + 1) * HID + c]);
    dst[i] = *(const uint32_t*)&h2;
}

// -------- warp GEMM tf32 (32x32 warp tile, dist-2 prefetch) --------
template <int NK8>
__device__ __forceinline__ void warp_gemm(const float* __restrict__ As, int sa,
                                          const float* __restrict__ Wp,
                                          int mrow0, int nq, int g, int tig, int lane,
                                          float acc[2][4][4])
{
    #pragma unroll
    for (int mm = 0; mm < 2; mm++)
        #pragma unroll
        for (int na = 0; na < 4; na++)
            #pragma unroll
            for (int i = 0; i < 4; i++) acc[mm][na][i] = 0.0f;

    const float4* wp = (const float4*)Wp + ((size_t)nq * 32 + lane) * 2;
    const float*  a0 = As + (mrow0 + g) * sa + tig;
    float4 c0 = __ldg(wp + 0), c1 = __ldg(wp + 1);
    float4 n0 = c0, n1 = c1;
    if (NK8 > 1) { n0 = __ldg(wp + 256); n1 = __ldg(wp + 257); }

    #pragma unroll 2
    for (int k8 = 0; k8 < NK8; k8++) {
        const float4 f0 = c0, f1 = c1;
        c0 = n0; c1 = n1;
        if (k8 + 2 < NK8) {
            n0 = __ldg(wp + (size_t)(k8 + 2) * 256);
            n1 = __ldg(wp + (size_t)(k8 + 2) * 256 + 1);
        }
        unsigned bc[4][2] = {
            { __float_as_uint(f0.x), __float_as_uint(f0.y) },
            { __float_as_uint(f0.z), __float_as_uint(f0.w) },
            { __float_as_uint(f1.x), __float_as_uint(f1.y) },
            { __float_as_uint(f1.z), __float_as_uint(f1.w) } };
        unsigned a[2][4];
        const float* ak = a0 + k8 * 8;
        #pragma unroll
        for (int mm = 0; mm < 2; mm++) {
            const float* am = ak + mm * 16 * sa;
            a[mm][0] = __float_as_uint(am[0]);
            a[mm][1] = __float_as_uint(am[8 * sa]);
            a[mm][2] = __float_as_uint(am[4]);
            a[mm][3] = __float_as_uint(am[8 * sa + 4]);
        }
        #pragma unroll
        for (int mm = 0; mm < 2; mm++)
            #pragma unroll
            for (int na = 0; na < 4; na++)
                mma8(acc[mm][na], a[mm], bc[na]);
    }
}

// -------- warp GEMM bf16 m16n8k16 (K=128 in 8 steps), A in SMEM bf16 --------
__device__ __forceinline__ void warp_gemm_bf16(const __nv_bfloat16* __restrict__ Ah,
                                               const uint32_t* __restrict__ Wp,
                                               int mrow0, int nq, int g, int tig, int lane,
                                               float acc[2][4][4])
{
    #pragma unroll
    for (int mm = 0; mm < 2; mm++)
        #pragma unroll
        for (int na = 0; na < 4; na++)
            #pragma unroll
            for (int i = 0; i < 4; i++) acc[mm][na][i] = 0.0f;

    const float4* wp = (const float4*)Wp + ((size_t)nq * 32 + lane) * 2;
    float4 c0 = __ldg(wp + 0),   c1 = __ldg(wp + 1);
    float4 n0 = __ldg(wp + 256), n1 = __ldg(wp + 257);

    #pragma unroll
    for (int k16 = 0; k16 < 8; k16++) {
        const float4 f0 = c0, f1 = c1;
        c0 = n0; c1 = n1;
        if (k16 + 2 < 8) {
            n0 = __ldg(wp + (size_t)(k16 + 2) * 256);
            n1 = __ldg(wp + (size_t)(k16 + 2) * 256 + 1);
        }
        unsigned bc[4][2] = {
            { __float_as_uint(f0.x), __float_as_uint(f0.y) },
            { __float_as_uint(f0.z), __float_as_uint(f0.w) },
            { __float_as_uint(f1.x), __float_as_uint(f1.y) },
            { __float_as_uint(f1.z), __float_as_uint(f1.w) } };
        unsigned a[2][4];
        #pragma unroll
        for (int mm = 0; mm < 2; mm++) {
            const __nv_bfloat16* base = Ah + (mrow0 + mm * 16 + g) * SH + k16 * 16 + 2 * tig;
            a[mm][0] = *(const uint32_t*)(base);
            a[mm][1] = *(const uint32_t*)(base + 8 * SH);
            a[mm][2] = *(const uint32_t*)(base + 8);
            a[mm][3] = *(const uint32_t*)(base + 8 * SH + 8);
        }
        #pragma unroll
        for (int mm = 0; mm < 2; mm++)
            #pragma unroll
            for (int na = 0; na < 4; na++)
                mma16(acc[mm][na], a[mm], bc[na]);
    }
}

// epilogue: dst[r][c] = tf32(silu(acc + bias[c]))
__device__ __forceinline__ void epi_silu(float* dst, int sd, const float* __restrict__ bias,
                                         int mrow0, int nq, int g, int tig, float acc[2][4][4])
{
    #pragma unroll
    for (int mm = 0; mm < 2; mm++) {
        const int r0 = mrow0 + mm * 16 + g;
        #pragma unroll
        for (int na = 0; na < 4; na++) {
            const int c = nq * 32 + na * 8 + tig * 2;
            const float b0 = __ldg(bias + c), b1 = __ldg(bias + c + 1);
            float2 v;
            v.x = to_tf32(siluf(acc[mm][na][0] + b0));
            v.y = to_tf32(siluf(acc[mm][na][1] + b1));
            *(float2*)(dst + r0 * sd + c) = v;
            v.x = to_tf32(siluf(acc[mm][na][2] + b0));
            v.y = to_tf32(siluf(acc[mm][na][3] + b1));
            *(float2*)(dst + (r0 + 8) * sd + c) = v;
        }
    }
}

// epilogue with SMEM additive term: dst = tf32(silu(acc + add[r][c] + bias[c]))
__device__ __forceinline__ void epi_silu_add(float* dst, int sd,
                                             const float* __restrict__ addb, int sadd,
                                             const float* __restrict__ bias,
                                             int mrow0, int nq, int g, int tig,
                                             float acc[2][4][4])
{
    #pragma unroll
    for (int mm = 0; mm < 2; mm++) {
        const int r0 = mrow0 + mm * 16 + g;
        #pragma unroll
        for (int na = 0; na < 4; na++) {
            const int c = nq * 32 + na * 8 + tig * 2;
            const float b0 = __ldg(bias + c), b1 = __ldg(bias + c + 1);
            const float2 u0 = *(const float2*)(addb + r0 * sadd + c);
            const float2 u1 = *(const float2*)(addb + (r0 + 8) * sadd + c);
            float2 v;
            v.x = to_tf32(siluf(acc[mm][na][0] + u0.x + b0));
            v.y = to_tf32(siluf(acc[mm][na][1] + u0.y + b1));
            *(float2*)(dst + r0 * sd + c) = v;
            v.x = to_tf32(siluf(acc[mm][na][2] + u1.x + b0));
            v.y = to_tf32(siluf(acc[mm][na][3] + u1.y + b1));
            *(float2*)(dst + (r0 + 8) * sd + c) = v;
        }
    }
}

// epilogue GEMM2: MT fp32 (no tf32 rounding) + MH bf16 copy for GEMM3
__device__ __forceinline__ void epi_silu_dual(float* mt, __nv_bfloat16* mh,
                                              const float* __restrict__ bias,
                                              int mrow0, int nq, int g, int tig,
                                              float acc[2][4][4])
{
    #pragma unroll
    for (int mm = 0; mm < 2; mm++) {
        const int r0 = mrow0 + mm * 16 + g;
        #pragma unroll
        for (int na = 0; na < 4; na++) {
            const int c = nq * 32 + na * 8 + tig * 2;
            const float b0 = __ldg(bias + c), b1 = __ldg(bias + c + 1);
            float2 v;
            v.x = siluf(acc[mm][na][0] + b0);
            v.y = siluf(acc[mm][na][1] + b1);
            *(float2*)(mt + r0 * SB + c) = v;
            *(__nv_bfloat162*)(mh + r0 * SH + c) = __floats2bfloat162_rn(v.x, v.y);
            v.x = siluf(acc[mm][na][2] + b0);
            v.y = siluf(acc[mm][na][3] + b1);
            *(float2*)(mt + (r0 + 8) * SB + c) = v;
            *(__nv_bfloat162*)(mh + (r0 + 8) * SH + c) = __floats2bfloat162_rn(v.x, v.y);
        }
    }
}

// -------- init: zero accumulators, detect idx dtype, pack weights --------
__global__ void init_kernel(const int* __restrict__ ei32,
                            const float* __restrict__ We1, const float* __restrict__ We2,
                            const float* __restrict__ Wx1, const float* __restrict__ Wn1,
                            const float* __restrict__ Wn2, int N)
{
    if (blockIdx.x == 0 && threadIdx.x == 0) {
        int flag = 1;
        for (int i = 0; i < 64; i++)
            if (ei32[2 * i + 1] != 0) { flag = 0; break; }
        g_idx64 = flag;
    }
    const int nMi = N * HID, nDx = N * 3;
    const int nW = HID * HID, nWf = FK * HID, nWh = HID * HID / 2;
    const int total = nMi + nDx + 5 * nW + nWf + nWh + nW;
    for (int i = blockIdx.x * blockDim.x + threadIdx.x; i < total;
         i += gridDim.x * blockDim.x) {
        int j = i;
        if (j < nMi) { g_mi[j] = 0.0f; continue; }                  j -= nMi;
        if (j < nDx) { g_dx[j] = 0.0f; continue; }                  j -= nDx;
        if (j < nW)  { pack_w(g_wdp,  We1, j, 0);   continue; }     j -= nW;
        if (j < nW)  { pack_w(g_wsp,  We1, j, HID); continue; }     j -= nW;
        if (j < nWf) { pack_w(g_w1f,  We1, j, 2 * HID); continue; } j -= nWf;
        if (j < nW)  { pack_w(g_w2c,  We2, j, 0);   continue; }     j -= nW;
        if (j < nWh) { pack_wh(g_wx1h, Wx1, j);     continue; }     j -= nWh;
        if (j < nW)  { pack_w(g_wn1m, Wn1, j, 0);   continue; }     j -= nW;
        if (j < nW)  { pack_w(g_wnp,  Wn1, j, HID); continue; }
        else         { pack_w(g_wn2c, Wn2, i - (total - nW), 0); }
    }
}

// -------- precompute: U = h@W_d, V = h@W_s, P = h@Wn1_h (per node) --------
__global__ void __launch_bounds__(512, 1)
pre_kernel(const float* __restrict__ h, int N)
{
    extern __shared__ float sm[];
    float* hA = sm;   // [TP][SB]

    const int tid  = threadIdx.x;
    const int lane = tid & 31, wid = tid >> 5;
    const int mrow0 = (wid & 3) * 32, nq = wid >> 2;
    const int g = lane >> 2, tig = lane & 3;
    const int n0 = blockIdx.x * TP;
    const int nN = min(TP, N - n0);

    #pragma unroll
    for (int it = 0; it < 8; it++) {
        const int r  = wid + it * 16;
        const int nd = n0 + min(r, nN - 1);
        const float4 vh = __ldg((const float4*)(h + (size_t)nd * HID) + lane);
        float4 w;
        w.x = to_tf32(vh.x); w.y = to_tf32(vh.y); w.z = to_tf32(vh.z); w.w = to_tf32(vh.w);
        *(float4*)(hA + r * SB + lane * 4) = w;
    }
    __syncthreads();

    float acc[2][4][4];
    const float* Wp[3] = { g_wdp, g_wsp, g_wnp };
    float* Gp[3];
    Gp[0] = g_u; Gp[1] = g_v; Gp[2] = g_p;

    #pragma unroll
    for (int m_ = 0; m_ < 3; m_++) {
        warp_gemm<HID / 8>(hA, SB, Wp[m_], mrow0, nq, g, tig, lane, acc);
        float* G = Gp[m_];
        #pragma unroll
        for (int mm = 0; mm < 2; mm++) {
            const int r0 = mrow0 + mm * 16 + g;
            #pragma unroll
            for (int na = 0; na < 4; na++) {
                const int c = nq * 32 + na * 8 + tig * 2;
                if (r0 < nN) {
                    float2 v; v.x = acc[mm][na][0]; v.y = acc[mm][na][1];
                    *(float2*)(G + (size_t)(n0 + r0) * HID + c) = v;
                }
                if (r0 + 8 < nN) {
                    float2 v; v.x = acc[mm][na][2]; v.y = acc[mm][na][3];
                    *(float2*)(G + (size_t)(n0 + r0 + 8) * HID + c) = v;
                }
            }
        }
    }
}

// -------- fused edge kernel: 64 edges/block, 256 threads, 2 blocks/SM --------
__global__ void __launch_bounds__(256, 2)
edge_kernel(const float* __restrict__ x,
            const void* __restrict__ eidx, const float* __restrict__ eattr,
            const float* __restrict__ be1, const float* __restrict__ be2,
            const float* __restrict__ Winf, const float* __restrict__ binf,
            const float* __restrict__ bx1, const float* __restrict__ Wx2, int E)
{
    extern __shared__ float sm[];
    float* FT   = sm;                       // [TE][SF] feat A-tile
    float* T1P  = sm + TE * SF;             // [TE][SB] U+V ; later MT (mij fp32)
    float* B1   = T1P + TE * SB;            // [TE][SB] t1 ; later GT
    __nv_bfloat16* MH = (__nv_bfloat16*)(B1 + TE * SB);   // [TE][SH] mij bf16
    int*   sSrc = (int*)((char*)MH + TE * SH * 2);
    int*   sDst = sSrc + TE;
    float* sD   = (float*)(sDst + TE);
    float* sRX  = sD + TE;                  // [TE][3]
    float* sEij = sRX + TE * 3;
    float* sXG  = sEij + TE;

    const int tid  = threadIdx.x;
    const int lane = tid & 31, wid = tid >> 5;
    const int mrow0 = (wid & 1) * 32, nq = wid >> 1;   // 2(M) x 4(N) warp grid
    const int g = lane >> 2, tig = lane & 3;
    const long long ebase = (long long)blockIdx.x * TE;
    const int nE = (int)min((long long)TE, (long long)E - ebase);

    // ---- phase A: indices, geometry, gaussian feats, edge_attr ----
    if (tid < TE) {
        const int e = tid;
        const long long eg = ebase + min(e, nE - 1);
        int s_, d_;
        if (g_idx64) {
            const long long* p = (const long long*)eidx;
            s_ = (int)p[eg]; d_ = (int)p[(long long)E + eg];
        } else {
            const int* p = (const int*)eidx;
            s_ = p[eg]; d_ = p[(long long)E + eg];
        }
        sSrc[e] = s_; sDst[e] = d_;
        float rx = x[d_ * 3 + 0] - x[s_ * 3 + 0];
        float ry = x[d_ * 3 + 1] - x[s_ * 3 + 1];
        float rz = x[d_ * 3 + 2] - x[s_ * 3 + 2];
        float dd = sqrtf(rx * rx + ry * ry + rz * rz + 1e-8f);
        sD[e] = dd;
        sRX[e * 3 + 0] = rx; sRX[e * 3 + 1] = ry; sRX[e * 3 + 2] = rz;
        const float step  = 10.0f / 19.0f;
        const float coeff = -0.5f / (step * step);
        #pragma unroll
        for (int gg = 0; gg < NG; gg++) {
            float t = dd - step * (float)gg;
            FT[e * SF + gg] = to_tf32(__expf(coeff * t * t));
        }
        #pragma unroll
        for (int a_ = 0; a_ < EF; a_++)
            FT[e * SF + NG + a_] = to_tf32(eattr[eg * EF + a_]);
    }
    __syncthreads();

    // ---- gather U[dst] + V[src] -> T1P (fp32 additive term, coalesced) ----
    #pragma unroll
    for (int it = 0; it < 8; it++) {
        const int e = wid + it * 8;
        const float4 a = __ldg((const float4*)(g_u + (size_t)sDst[e] * HID) + lane);
        const float4 b = __ldg((const float4*)(g_v + (size_t)sSrc[e] * HID) + lane);
        float4 w;
        w.x = a.x + b.x; w.y = a.y + b.y; w.z = a.z + b.z; w.w = a.w + b.w;
        *(float4*)(T1P + e * SB + lane * 4) = w;
    }
    __syncthreads();

    float acc[2][4][4];

    // ---- GEMM1 (feat only, 3 k8): t1 = silu(feat@W_f + U+V + be1) -> B1 ----
    warp_gemm<FK / 8>(FT, SF, g_w1f, mrow0, nq, g, tig, lane, acc);
    epi_silu_add(B1, SB, T1P, SB, be1, mrow0, nq, g, tig, acc);
    __syncthreads();

    // ---- GEMM2: mij = silu(t1 @ We2 + be2) -> MT fp32 + MH bf16 ----
    warp_gemm<HID / 8>(B1, SB, g_w2c, mrow0, nq, g, tig, lane, acc);
    float* MT = T1P;   // overlays UV (fully consumed)
    epi_silu_dual(MT, MH, be2, mrow0, nq, g, tig, acc);
    __syncthreads();   // S1: MT + MH visible

    // ---- eij = sigmoid(mij . Winf + binf) ----
    if (tid < TE) {
        float s = binf[0];
        #pragma unroll 4
        for (int k = 0; k < HID; k++)
            s += MT[tid * SB + k] * __ldg(&Winf[k]);
        sEij[tid] = __fdividef(1.0f, 1.0f + __expf(-s));
    }

    // ---- GEMM3 (bf16 m16n8k16): gx = silu(mij @ Wx1 + bx1) -> GT ----
    warp_gemm_bf16(MH, g_wx1h, mrow0, nq, g, tig, lane, acc);
    float* GT = B1;
    epi_silu(GT, SB, bx1, mrow0, nq, g, tig, acc);
    __syncthreads();   // S2: GT + sEij visible

    // ---- xg = tanh(gx . Wx2) ----
    if (tid < TE) {
        float s = 0.0f;
        #pragma unroll 4
        for (int k = 0; k < HID; k++)
            s += GT[tid * SB + k] * __ldg(&Wx2[k]);
        sXG[tid] = tanhf(s);
    }

    // ---- scatter: mi[dst] += mij*eij via red.global.add.v4.f32 ----
    #pragma unroll 2
    for (int i = 0; i < 8; i++) {
        const int e = wid * 8 + i;
        if (e < nE) {
            const float4 v = *(const float4*)(MT + e * SB + lane * 4);
            const float sc = sEij[e];
            red4(&g_mi[(size_t)sDst[e] * HID + lane * 4],
                 v.x * sc, v.y * sc, v.z * sc, v.w * sc);
        }
    }
    // ---- scatter: dx[dst] += rel_x/(d+1)*xg ----
    if (tid < nE) {
        const int e = tid, d_ = sDst[e];
        const float f = __fdividef(sXG[e], sD[e] + 1.0f);
        atomicAdd(&g_dx[d_ * 3 + 0], sRX[e * 3 + 0] * f);
        atomicAdd(&g_dx[d_ * 3 + 1], sRX[e * 3 + 1] * f);
        atomicAdd(&g_dx[d_ * 3 + 2], sRX[e * 3 + 2] * f);
    }
}

// -------- node kernel: h_out = h + MLP([mi, h]); x_out = x + dx*mask --------
__global__ void __launch_bounds__(256, 2)
node_kernel(const float* __restrict__ h, const float* __restrict__ x,
            const float* __restrict__ mask,
            const float* __restrict__ bn1, const float* __restrict__ bn2,
            float* __restrict__ out, int N)
{
    extern __shared__ float sm[];
    float* zA = sm;                 // [TN][SB] : mi (tf32)
    float* PB = sm + TN * SB;       // [TN][SB] : P = h@Wn1_h (fp32 additive)
    float* B1 = PB + TN * SB;       // [TN][SB] : u

    const int tid  = threadIdx.x;
    const int lane = tid & 31, wid = tid >> 5;
    const int mrow0 = (wid & 1) * 32, nq = wid >> 1;
    const int g = lane >> 2, tig = lane & 3;
    const int n0 = blockIdx.x * TN;
    const int nN = min(TN, N - n0);

    #pragma unroll
    for (int it = 0; it < 8; it++) {
        const int r  = wid + it * 8;
        const int nd = n0 + min(r, nN - 1);
        const float4 vm = __ldg((const float4*)(g_mi + (size_t)nd * HID) + lane);
        const float4 vp = __ldg((const float4*)(g_p + (size_t)nd * HID) + lane);
        float4 w;
        w.x = to_tf32(vm.x); w.y = to_tf32(vm.y); w.z = to_tf32(vm.z); w.w = to_tf32(vm.w);
        *(float4*)(zA + r * SB + lane * 4) = w;
        *(float4*)(PB + r * SB + lane * 4) = vp;
    }
    __syncthreads();

    float acc[2][4][4];

    warp_gemm<HID / 8>(zA, SB, g_wn1m, mrow0, nq, g, tig, lane, acc);
    epi_silu_add(B1, SB, PB, SB, bn1, mrow0, nq, g, tig, acc);
    __syncthreads();

    warp_gemm<HID / 8>(B1, SB, g_wn2c, mrow0, nq, g, tig, lane, acc);
    {
        #pragma unroll
        for (int mm = 0; mm < 2; mm++) {
            const int r0 = mrow0 + mm * 16 + g;
            #pragma unroll
            for (int na = 0; na < 4; na++) {
                const int c = nq * 32 + na * 8 + tig * 2;
                const float b0 = __ldg(bn2 + c), b1 = __ldg(bn2 + c + 1);
                if (r0 < nN) {
                    const size_t o = (size_t)(n0 + r0) * HID + c;
                    out[o]     = h[o]     + acc[mm][na][0] + b0;
                    out[o + 1] = h[o + 1] + acc[mm][na][1] + b1;
                }
                if (r0 + 8 < nN) {
                    const size_t o = (size_t)(n0 + r0 + 8) * HID + c;
                    out[o]     = h[o]     + acc[mm][na][2] + b0;
                    out[o + 1] = h[o + 1] + acc[mm][na][3] + b1;
                }
            }
        }
    }
    if (tid < nN) {
        const int nd = n0 + tid;
        const float m = mask[nd];
        const size_t xo = (size_t)N * HID;
        out[xo + nd * 3 + 0] = x[nd * 3 + 0] + g_dx[nd * 3 + 0] * m;
        out[xo + nd * 3 + 1] = x[nd * 3 + 1] + g_dx[nd * 3 + 1] * m;
        out[xo + nd * 3 + 2] = x[nd * 3 + 2] + g_dx[nd * 3 + 2] * m;
    }
}

extern "C" void kernel_launch(void* const* d_in, const int* in_sizes, int n_in,
                              void* d_out, int out_size) {
    const float* h    = (const float*)d_in[0];
    const float* x    = (const float*)d_in[1];
    const void*  ei   = d_in[2];
    const float* mask = (const float*)d_in[3];
    const float* ea   = (const float*)d_in[4];
    const float* We1  = (const float*)d_in[5];
    const float* be1  = (const float*)d_in[6];
    const float* We2  = (const float*)d_in[7];
    const float* be2  = (const float*)d_in[8];
    const float* Winf = (const float*)d_in[9];
    const float* binf = (const float*)d_in[10];
    const float* Wx1  = (const float*)d_in[11];
    const float* bx1  = (const float*)d_in[12];
    const float* Wx2  = (const float*)d_in[13];
    const float* Wn1  = (const float*)d_in[14];
    const float* bn1  = (const float*)d_in[15];
    const float* Wn2  = (const float*)d_in[16];
    const float* bn2  = (const float*)d_in[17];
    float* out = (float*)d_out;

    const int N = in_sizes[0] / HID;
    const int E = in_sizes[2] / 2;

    const int pre_smem  = TP * SB * 4;
    const int edge_smem = (TE * SF + 2 * TE * SB + TE * 8) * 4 + TE * SH * 2;   // ~96 KB
    const int node_smem = 3 * TN * SB * 4;

    cudaFuncSetAttribute(pre_kernel,  cudaFuncAttributeMaxDynamicSharedMemorySize, pre_smem);
    cudaFuncSetAttribute(edge_kernel, cudaFuncAttributeMaxDynamicSharedMemorySize, edge_smem);
    cudaFuncSetAttribute(node_kernel, cudaFuncAttributeMaxDynamicSharedMemorySize, node_smem);

    init_kernel<<<2048, 256>>>((const int*)ei, We1, We2, Wx1, Wn1, Wn2, N);
    pre_kernel<<<(N + TP - 1) / TP, 512, pre_smem>>>(h, N);
    edge_kernel<<<(E + TE - 1) / TE, 256, edge_smem>>>(
        x, ei, ea, be1, be2, Winf, binf, bx1, Wx2, E);
    node_kernel<<<(N + TN - 1) / TN, 256, node_smem>>>(
        h, x, mask, bn1, bn2, out, N);
}